// round 2
// baseline (speedup 1.0000x reference)
#include <cuda_runtime.h>

// Problem constants (fixed by the dataset)
constexpr int E  = 512;   // embedding
constexpr int H  = 8;     // heads
constexpr int S  = 64;    // d_head
constexpr int TR = 64;    // rows per block
constexpr int LDX = 520;  // padded shared stride (floats), 16B-aligned rows, bank-rotating
constexpr int KC = 32;    // k-panel for phase-2 GEMM
constexpr int THREADS = 256;

__global__ __launch_bounds__(THREADS, 1)
void sparse_attn_fused(const float* __restrict__ x,
                       const float* __restrict__ Wq, const float* __restrict__ bq,
                       const float* __restrict__ Wk, const float* __restrict__ bk,
                       const float* __restrict__ Wv, const float* __restrict__ bv,
                       const float* __restrict__ Wu, const float* __restrict__ bu,
                       float* __restrict__ out, int Nrows)
{
    extern __shared__ float smem[];
    float* sX = smem;                 // [TR][LDX] : x tile, then overwritten with a*v
    float* sW = smem + TR * LDX;      // phase1: Wq|Wk|Wv (3*64*64) ; phase2: Wu panel [KC][E]

    const int tid  = threadIdx.x;
    const int lane = tid & 31;
    const int w    = tid >> 5;        // warp id 0..7
    const int row0 = blockIdx.x * TR;
    const int rmax = min(TR, Nrows - row0);   // rows valid in this tile (normally 64)

    // ---- load x tile [TR][E] into shared (zero-fill beyond rmax) ----
    {
        const float4* xg = reinterpret_cast<const float4*>(x + (size_t)row0 * E);
        for (int idx = tid; idx < TR * (E / 4); idx += THREADS) {
            int r  = idx >> 7;        // E/4 = 128 float4 per row
            int c4 = idx & 127;
            float4 v;
            if (r < rmax) v = xg[r * (E / 4) + c4];
            else          v = make_float4(0.f, 0.f, 0.f, 0.f);
            *reinterpret_cast<float4*>(&sX[r * LDX + c4 * 4]) = v;
        }
    }
    __syncthreads();

    const float inv_sqrt_e = 0.04419417382415922f;  // 1/sqrt(512)

    // =========================== Phase 1: per-head QKV + softmax(a)*v ===========================
    for (int h = 0; h < H; ++h) {
        // stage Wq/Wk/Wv for head h into shared
        {
            const float4* wq = reinterpret_cast<const float4*>(Wq + h * S * S);
            const float4* wk = reinterpret_cast<const float4*>(Wk + h * S * S);
            const float4* wv = reinterpret_cast<const float4*>(Wv + h * S * S);
            float4* q4 = reinterpret_cast<float4*>(sW);
            float4* k4 = reinterpret_cast<float4*>(sW + S * S);
            float4* v4 = reinterpret_cast<float4*>(sW + 2 * S * S);
            for (int idx = tid; idx < S * S / 4; idx += THREADS) {
                q4[idx] = wq[idx];
                k4[idx] = wk[idx];
                v4[idx] = wv[idx];
            }
        }
        __syncthreads();

        // each lane owns t-pair (2*lane, 2*lane+1); biases constant per head
        float2 bqv = *reinterpret_cast<const float2*>(bq + h * S + 2 * lane);
        float2 bkv = *reinterpret_cast<const float2*>(bk + h * S + 2 * lane);
        float2 bvv = *reinterpret_cast<const float2*>(bv + h * S + 2 * lane);

        const float* sWq = sW;
        const float* sWk = sW + S * S;
        const float* sWv = sW + 2 * S * S;

        // warp w handles rows [w*8, w*8+8), in two groups of 4
        #pragma unroll
        for (int g = 0; g < 2; ++g) {
            const int rbase = w * 8 + g * 4;
            float q[4][2], k[4][2], v[4][2];
            #pragma unroll
            for (int j = 0; j < 4; ++j) {
                q[j][0] = bqv.x; q[j][1] = bqv.y;
                k[j][0] = bkv.x; k[j][1] = bkv.y;
                v[j][0] = bvv.x; v[j][1] = bvv.y;
            }

            #pragma unroll 8
            for (int s = 0; s < S; ++s) {
                float2 wq2 = *reinterpret_cast<const float2*>(&sWq[s * S + 2 * lane]);
                float2 wk2 = *reinterpret_cast<const float2*>(&sWk[s * S + 2 * lane]);
                float2 wv2 = *reinterpret_cast<const float2*>(&sWv[s * S + 2 * lane]);
                #pragma unroll
                for (int j = 0; j < 4; ++j) {
                    float xv = sX[(rbase + j) * LDX + h * S + s];   // broadcast LDS
                    q[j][0] += xv * wq2.x; q[j][1] += xv * wq2.y;
                    k[j][0] += xv * wk2.x; k[j][1] += xv * wk2.y;
                    v[j][0] += xv * wv2.x; v[j][1] += xv * wv2.y;
                }
            }

            // softmax over the 64 t-values (spread across 32 lanes x 2 regs), then *v
            #pragma unroll
            for (int j = 0; j < 4; ++j) {
                float p0 = q[j][0] * k[j][0] * inv_sqrt_e;
                float p1 = q[j][1] * k[j][1] * inv_sqrt_e;
                float m = fmaxf(p0, p1);
                #pragma unroll
                for (int off = 16; off > 0; off >>= 1)
                    m = fmaxf(m, __shfl_xor_sync(0xffffffffu, m, off));
                float e0 = __expf(p0 - m);
                float e1 = __expf(p1 - m);
                float ssum = e0 + e1;
                #pragma unroll
                for (int off = 16; off > 0; off >>= 1)
                    ssum += __shfl_xor_sync(0xffffffffu, ssum, off);
                float inv = 1.0f / ssum;
                float2 res = make_float2(e0 * inv * v[j][0], e1 * inv * v[j][1]);
                // overwrite consumed x slice in place (warp-private rows, reads all done)
                *reinterpret_cast<float2*>(&sX[(rbase + j) * LDX + h * S + 2 * lane]) = res;
            }
        }
        __syncthreads();   // before next head's weight reload (and before phase 2)
    }

    // =========================== Phase 2: out = t(64x512) @ Wu(512x512) + bu ====================
    // thread (ty=w, tx=lane): rows ty*8..+7, cols {g*128 + tx*4 .. +3} for g=0..3 (16 cols)
    const int tx = lane;
    const int ty = w;

    float acc[8][16];
    #pragma unroll
    for (int i = 0; i < 8; ++i)
        #pragma unroll
        for (int jj = 0; jj < 16; ++jj) acc[i][jj] = 0.f;

    for (int k0 = 0; k0 < E; k0 += KC) {
        // stage Wu[k0..k0+KC)[0..E) into shared
        const float4* wug = reinterpret_cast<const float4*>(Wu + (size_t)k0 * E);
        float4* sw4 = reinterpret_cast<float4*>(sW);
        for (int idx = tid; idx < KC * E / 4; idx += THREADS)
            sw4[idx] = wug[idx];
        __syncthreads();

        #pragma unroll 4
        for (int kk = 0; kk < KC; ++kk) {
            float tv[8];
            #pragma unroll
            for (int i = 0; i < 8; ++i)
                tv[i] = sX[(ty * 8 + i) * LDX + k0 + kk];   // broadcast LDS
            #pragma unroll
            for (int g = 0; g < 4; ++g) {
                float4 wu4 = *reinterpret_cast<const float4*>(&sW[kk * E + g * 128 + tx * 4]);
                #pragma unroll
                for (int i = 0; i < 8; ++i) {
                    acc[i][g * 4 + 0] += tv[i] * wu4.x;
                    acc[i][g * 4 + 1] += tv[i] * wu4.y;
                    acc[i][g * 4 + 2] += tv[i] * wu4.z;
                    acc[i][g * 4 + 3] += tv[i] * wu4.w;
                }
            }
        }
        __syncthreads();
    }

    // epilogue: + bu, store coalesced float4
    #pragma unroll
    for (int g = 0; g < 4; ++g) {
        float4 bv4 = *reinterpret_cast<const float4*>(&bu[g * 128 + tx * 4]);
        #pragma unroll
        for (int i = 0; i < 8; ++i) {
            int r = ty * 8 + i;
            if (r < rmax) {
                float4 o;
                o.x = acc[i][g * 4 + 0] + bv4.x;
                o.y = acc[i][g * 4 + 1] + bv4.y;
                o.z = acc[i][g * 4 + 2] + bv4.z;
                o.w = acc[i][g * 4 + 3] + bv4.w;
                *reinterpret_cast<float4*>(&out[(size_t)(row0 + r) * E + g * 128 + tx * 4]) = o;
            }
        }
    }
}

extern "C" void kernel_launch(void* const* d_in, const int* in_sizes, int n_in,
                              void* d_out, int out_size)
{
    const float* x  = (const float*)d_in[0];
    const float* Wq = (const float*)d_in[1];
    const float* bq = (const float*)d_in[2];
    const float* Wk = (const float*)d_in[3];
    const float* bk = (const float*)d_in[4];
    const float* Wv = (const float*)d_in[5];
    const float* bv = (const float*)d_in[6];
    const float* Wu = (const float*)d_in[7];
    const float* bu = (const float*)d_in[8];
    float* out = (float*)d_out;

    const int Nrows = in_sizes[0] / E;   // 131072

    const size_t smem_bytes = (size_t)(TR * LDX + KC * E) * sizeof(float);  // 198656 B
    cudaFuncSetAttribute(sparse_attn_fused,
                         cudaFuncAttributeMaxDynamicSharedMemorySize,
                         (int)smem_bytes);

    const int grid = (Nrows + TR - 1) / TR;
    sparse_attn_fused<<<grid, THREADS, smem_bytes>>>(
        x, Wq, bq, Wk, bk, Wv, bv, Wu, bu, out, Nrows);
}

// round 4
// speedup vs baseline: 3.3337x; 3.3337x over previous
#include <cuda_runtime.h>
#include <cuda_bf16.h>
#include <cstdint>

// ============================ problem constants ============================
constexpr int E = 512, H = 8, S = 64, TM = 128, MAXN = 131072;

// ============================ device scratch ===============================
// t tiles: [1024 blk][8 h][128x64 bf16 SW128-swizzled tile = 16KB], hi and lo
__device__ __align__(1024) __nv_bfloat16 g_t_hi[(size_t)MAXN * E];
__device__ __align__(1024) __nv_bfloat16 g_t_lo[(size_t)MAXN * E];
// per head: q_hi,q_lo,k_hi,k_lo,v_hi,v_lo — 64x64 bf16 [s][t] SW128 tiles (8KB each)
__device__ __align__(1024) unsigned char g_wqkv[H * 6 * 8192];
// Wu blocks: [kc 0..7][nh 0..1] -> [64 k][256 n] bf16, 512B rows, swz512 (32KB each)
__device__ __align__(1024) unsigned char g_wub_hi[16 * 32768];
__device__ __align__(1024) unsigned char g_wub_lo[16 * 32768];

// ============================ helpers ======================================
__device__ __forceinline__ uint32_t smem_u32(const void* p) {
    uint32_t a;
    asm("{ .reg .u64 t; cvta.to.shared.u64 t, %1; cvt.u32.u64 %0, t; }" : "=r"(a) : "l"(p));
    return a;
}
__host__ __device__ __forceinline__ uint32_t swz128(uint32_t o) { return o ^ ((o >> 3) & 0x70); }
__host__ __device__ __forceinline__ uint32_t swz512(uint32_t o) { return o ^ ((o >> 5) & 0x70); }

__device__ __forceinline__ void ldsm_x4(uint32_t (&r)[4], uint32_t a) {
    asm volatile("ldmatrix.sync.aligned.m8n8.x4.shared.b16 {%0,%1,%2,%3}, [%4];"
        : "=r"(r[0]), "=r"(r[1]), "=r"(r[2]), "=r"(r[3]) : "r"(a));
}
__device__ __forceinline__ void ldsm_x4t(uint32_t (&r)[4], uint32_t a) {
    asm volatile("ldmatrix.sync.aligned.m8n8.x4.trans.shared.b16 {%0,%1,%2,%3}, [%4];"
        : "=r"(r[0]), "=r"(r[1]), "=r"(r[2]), "=r"(r[3]) : "r"(a));
}
__device__ __forceinline__ void mma16816(float (&d)[4], const uint32_t (&a)[4],
                                         uint32_t b0, uint32_t b1) {
    asm volatile("mma.sync.aligned.m16n8k16.row.col.f32.bf16.bf16.f32 "
        "{%0,%1,%2,%3}, {%4,%5,%6,%7}, {%8,%9}, {%0,%1,%2,%3};"
        : "+f"(d[0]), "+f"(d[1]), "+f"(d[2]), "+f"(d[3])
        : "r"(a[0]), "r"(a[1]), "r"(a[2]), "r"(a[3]), "r"(b0), "r"(b1));
}
__device__ __forceinline__ void cp16(uint32_t dst, const void* src) {
    asm volatile("cp.async.cg.shared.global [%0], [%1], 16;" :: "r"(dst), "l"(src));
}
#define CP_COMMIT() asm volatile("cp.async.commit_group;" ::: "memory")
#define CP_WAIT(n)  asm volatile("cp.async.wait_group %0;" :: "n"(n) : "memory")

__device__ __forceinline__ void split2(float x, __nv_bfloat16& hi, __nv_bfloat16& lo) {
    hi = __float2bfloat16(x);
    lo = __float2bfloat16(x - __bfloat162float(hi));
}
__device__ __forceinline__ uint32_t pack2(__nv_bfloat16 a, __nv_bfloat16 b) {
    __nv_bfloat162 p(a, b);
    return *reinterpret_cast<uint32_t*>(&p);
}

// ============================ prep kernels =================================
__global__ void prep_qkv(const float* __restrict__ Wq, const float* __restrict__ Wk,
                         const float* __restrict__ Wv) {
    int idx = blockIdx.x * 256 + threadIdx.x;
    if (idx >= H * 3 * S * S) return;
    int h = idx / (3 * S * S);
    int rem = idx % (3 * S * S);
    int o = rem / (S * S);
    int st = rem % (S * S);
    int s = st >> 6, t = st & 63;
    const float* W = (o == 0) ? Wq : ((o == 1) ? Wk : Wv);
    float v = W[(h * S + s) * S + t];
    __nv_bfloat16 hi, lo; split2(v, hi, lo);
    uint32_t off = swz128((uint32_t)(s * 128 + t * 2));
    unsigned char* base = g_wqkv + (size_t)(h * 6 + o * 2) * 8192;
    *reinterpret_cast<__nv_bfloat16*>(base + off)        = hi;
    *reinterpret_cast<__nv_bfloat16*>(base + 8192 + off) = lo;
}
__global__ void prep_wu(const float* __restrict__ Wu) {
    int idx = blockIdx.x * 256 + threadIdx.x;
    if (idx >= E * E) return;
    int k = idx >> 9, n = idx & 511;
    float v = Wu[idx];
    __nv_bfloat16 hi, lo; split2(v, hi, lo);
    int kc = k >> 6, kk = k & 63, nh = n >> 8, nn = n & 255;
    uint32_t off = swz512((uint32_t)(kk * 512 + nn * 2));
    size_t base = (size_t)(kc * 2 + nh) * 32768;
    *reinterpret_cast<__nv_bfloat16*>(g_wub_hi + base + off) = hi;
    *reinterpret_cast<__nv_bfloat16*>(g_wub_lo + base + off) = lo;
}

// ============================ kernel 1: QKV + softmax -> t =================
// smem: X_hi[128x64]@0 (16K) | X_lo@16384 | W 6 tiles@32768 (48K) = 81920 B
constexpr uint32_t K1_XHI = 0, K1_XLO = 16384, K1_W = 32768, K1_SMEM = 81920;

__global__ __launch_bounds__(256, 1)
void qkv_softmax_kernel(const float* __restrict__ x,
                        const float* __restrict__ bq, const float* __restrict__ bk,
                        const float* __restrict__ bv)
{
    extern __shared__ unsigned char smem[];
    const uint32_t sb = smem_u32(smem);
    const int tid = threadIdx.x, lane = tid & 31, wid = tid >> 5;
    const int row0 = blockIdx.x * TM;
    const float SC = 0.04419417382415922f;  // 1/sqrt(512)

    const int g = lane >> 2;               // row within m8 group
    const int qd = lane & 3;               // quad lane -> col pair
    const uint32_t aRow = (uint32_t)(wid * 16 + (lane & 15));
    const uint32_t hiSel = (uint32_t)((lane >> 4) << 4);

    for (int h = 0; h < H; ++h) {
        // ---- stage x slice -> bf16 hi/lo swizzled ----
        #pragma unroll
        for (int i = 0; i < 8; ++i) {
            int idx = tid + i * 256;                 // 2048 = 128 rows x 16 float4
            int r = idx >> 4, c4 = idx & 15;
            float4 xv = *reinterpret_cast<const float4*>(
                x + (size_t)(row0 + r) * E + h * S + c4 * 4);
            __nv_bfloat16 h0,l0,h1,l1,h2,l2,h3,l3;
            split2(xv.x,h0,l0); split2(xv.y,h1,l1); split2(xv.z,h2,l2); split2(xv.w,h3,l3);
            uint32_t off = swz128((uint32_t)(r * 128 + c4 * 8));
            *reinterpret_cast<uint2*>(smem + K1_XHI + off) = make_uint2(pack2(h0,h1), pack2(h2,h3));
            *reinterpret_cast<uint2*>(smem + K1_XLO + off) = make_uint2(pack2(l0,l1), pack2(l2,l3));
        }
        // ---- stage W (pre-swizzled, contiguous 48KB) ----
        {
            const char* src = (const char*)g_wqkv + (size_t)h * 49152;
            #pragma unroll
            for (int i = 0; i < 12; ++i) {
                uint32_t o = (uint32_t)(tid + i * 256) * 16;
                cp16(sb + K1_W + o, src + o);
            }
            CP_COMMIT(); CP_WAIT(0);
        }
        __syncthreads();

        // ---- mma: acc[q,k,v][8 ntiles][4] ----
        float acc[3][8][4];
        #pragma unroll
        for (int o = 0; o < 3; ++o)
            #pragma unroll
            for (int nt = 0; nt < 8; ++nt)
                #pragma unroll
                for (int c = 0; c < 4; ++c) acc[o][nt][c] = 0.f;

        #pragma unroll
        for (int ks = 0; ks < 4; ++ks) {
            uint32_t aHi[4], aLo[4];
            uint32_t aoff = swz128(aRow * 128 + (uint32_t)ks * 32 + hiSel);
            ldsm_x4(aHi, sb + K1_XHI + aoff);
            ldsm_x4(aLo, sb + K1_XLO + aoff);
            #pragma unroll
            for (int o = 0; o < 3; ++o) {
                #pragma unroll
                for (int ntp = 0; ntp < 4; ++ntp) {
                    uint32_t boff = swz128((uint32_t)(ks * 16 + (lane & 15)) * 128
                                           + (uint32_t)ntp * 32 + hiSel);
                    uint32_t bHi[4], bLo[4];
                    ldsm_x4t(bHi, sb + K1_W + (uint32_t)(o * 2) * 8192 + boff);
                    ldsm_x4t(bLo, sb + K1_W + (uint32_t)(o * 2 + 1) * 8192 + boff);
                    mma16816(acc[o][2*ntp],   aHi, bHi[0], bHi[1]);
                    mma16816(acc[o][2*ntp+1], aHi, bHi[2], bHi[3]);
                    mma16816(acc[o][2*ntp],   aLo, bHi[0], bHi[1]);
                    mma16816(acc[o][2*ntp+1], aLo, bHi[2], bHi[3]);
                    mma16816(acc[o][2*ntp],   aHi, bLo[0], bLo[1]);
                    mma16816(acc[o][2*ntp+1], aHi, bLo[2], bLo[3]);
                }
            }
        }

        // ---- softmax over the 64 t-values per row, t = a*v, store hi/lo ----
        char* tbHi = (char*)g_t_hi + ((size_t)blockIdx.x * H + h) * 16384;
        char* tbLo = (char*)g_t_lo + ((size_t)blockIdx.x * H + h) * 16384;
        const float* bqh = bq + h * S;
        const float* bkh = bk + h * S;
        const float* bvh = bv + h * S;

        #pragma unroll
        for (int rr = 0; rr < 2; ++rr) {
            float ev[16], vv[16];
            float ssum = 0.f;
            #pragma unroll
            for (int nt = 0; nt < 8; ++nt) {
                int col0 = nt * 8 + qd * 2;
                float2 bq2 = *reinterpret_cast<const float2*>(bqh + col0);
                float2 bk2 = *reinterpret_cast<const float2*>(bkh + col0);
                float2 bv2 = *reinterpret_cast<const float2*>(bvh + col0);
                float q0 = acc[0][nt][rr*2+0] + bq2.x, q1 = acc[0][nt][rr*2+1] + bq2.y;
                float k0 = acc[1][nt][rr*2+0] + bk2.x, k1 = acc[1][nt][rr*2+1] + bk2.y;
                float e0 = __expf(q0 * k0 * SC), e1 = __expf(q1 * k1 * SC);
                ev[nt*2] = e0; ev[nt*2+1] = e1; ssum += e0 + e1;
                vv[nt*2]   = acc[2][nt][rr*2+0] + bv2.x;
                vv[nt*2+1] = acc[2][nt][rr*2+1] + bv2.y;
            }
            ssum += __shfl_xor_sync(0xffffffffu, ssum, 1);
            ssum += __shfl_xor_sync(0xffffffffu, ssum, 2);
            float inv = 1.0f / ssum;
            int rt = wid * 16 + g + rr * 8;    // tile-local row
            #pragma unroll
            for (int nt = 0; nt < 8; ++nt) {
                float t0 = ev[nt*2]   * inv * vv[nt*2];
                float t1 = ev[nt*2+1] * inv * vv[nt*2+1];
                __nv_bfloat16 h0,l0,h1,l1;
                split2(t0,h0,l0); split2(t1,h1,l1);
                uint32_t off = swz128((uint32_t)(rt * 128 + nt * 16 + qd * 4));
                *reinterpret_cast<uint32_t*>(tbHi + off) = pack2(h0, h1);
                *reinterpret_cast<uint32_t*>(tbLo + off) = pack2(l0, l1);
            }
        }
        __syncthreads();   // before overwriting smem for next head
    }
}

// ============================ kernel 2: out = t @ Wu + bu ==================
// buf layout: [A_hi 16K][A_lo 16K][B_hi 32K][B_lo 32K] = 96KB; two buffers
constexpr uint32_t K2_BUF = 98304, K2_SMEM = 196608;

__global__ __launch_bounds__(256, 1)
void unify_gemm_kernel(const float* __restrict__ bu, float* __restrict__ out)
{
    extern __shared__ unsigned char smem[];
    const uint32_t sb = smem_u32(smem);
    const int tid = threadIdx.x, lane = tid & 31, wid = tid >> 5;
    const int row0 = blockIdx.x * TM;
    const int g = lane >> 2, qd = lane & 3;
    const uint32_t aRow = (uint32_t)(wid * 16 + (lane & 15));
    const uint32_t hiSel = (uint32_t)((lane >> 4) << 4);

    auto load_chunk = [&](int it, int buf) {
        int nh = it >> 3, kc = it & 7;
        uint32_t d = sb + (uint32_t)buf * K2_BUF;
        const char* aHi = (const char*)g_t_hi + (size_t)blockIdx.x * 131072 + (size_t)kc * 16384;
        const char* aLo = (const char*)g_t_lo + (size_t)blockIdx.x * 131072 + (size_t)kc * 16384;
        const char* bHi = (const char*)g_wub_hi + (size_t)(kc * 2 + nh) * 32768;
        const char* bLo = (const char*)g_wub_lo + (size_t)(kc * 2 + nh) * 32768;
        #pragma unroll
        for (int i = 0; i < 4; ++i) {
            uint32_t o = (uint32_t)(tid + i * 256) * 16;
            cp16(d + o,         aHi + o);
            cp16(d + 16384 + o, aLo + o);
        }
        #pragma unroll
        for (int i = 0; i < 8; ++i) {
            uint32_t o = (uint32_t)(tid + i * 256) * 16;
            cp16(d + 32768 + o, bHi + o);
            cp16(d + 65536 + o, bLo + o);
        }
    };

    load_chunk(0, 0);
    CP_COMMIT();

    for (int nh = 0; nh < 2; ++nh) {
        float acc[32][4];
        #pragma unroll
        for (int nt = 0; nt < 32; ++nt)
            #pragma unroll
            for (int c = 0; c < 4; ++c) acc[nt][c] = 0.f;

        for (int kc = 0; kc < 8; ++kc) {
            int it = nh * 8 + kc;
            if (it + 1 < 16) { load_chunk(it + 1, (it + 1) & 1); CP_COMMIT(); CP_WAIT(1); }
            else             { CP_WAIT(0); }
            __syncthreads();

            uint32_t base = sb + (uint32_t)(it & 1) * K2_BUF;
            #pragma unroll
            for (int ks = 0; ks < 4; ++ks) {
                uint32_t aHi[4], aLo[4];
                uint32_t aoff = swz128(aRow * 128 + (uint32_t)ks * 32 + hiSel);
                ldsm_x4(aHi, base + aoff);
                ldsm_x4(aLo, base + 16384 + aoff);
                #pragma unroll
                for (int ntp = 0; ntp < 16; ++ntp) {
                    uint32_t boff = swz512((uint32_t)(ks * 16 + (lane & 15)) * 512
                                           + (uint32_t)ntp * 32 + hiSel);
                    uint32_t bHi[4], bLo[4];
                    ldsm_x4t(bHi, base + 32768 + boff);
                    ldsm_x4t(bLo, base + 65536 + boff);
                    mma16816(acc[2*ntp],   aHi, bHi[0], bHi[1]);
                    mma16816(acc[2*ntp+1], aHi, bHi[2], bHi[3]);
                    mma16816(acc[2*ntp],   aLo, bHi[0], bHi[1]);
                    mma16816(acc[2*ntp+1], aLo, bHi[2], bHi[3]);
                    mma16816(acc[2*ntp],   aHi, bLo[0], bLo[1]);
                    mma16816(acc[2*ntp+1], aHi, bLo[2], bLo[3]);
                }
            }
            __syncthreads();
        }

        // epilogue for this N-half
        #pragma unroll
        for (int nt = 0; nt < 32; ++nt) {
            int col0 = nh * 256 + nt * 8 + qd * 2;
            float2 bb = *reinterpret_cast<const float2*>(bu + col0);
            int r0 = row0 + wid * 16 + g;
            float2 o0 = make_float2(acc[nt][0] + bb.x, acc[nt][1] + bb.y);
            float2 o1 = make_float2(acc[nt][2] + bb.x, acc[nt][3] + bb.y);
            *reinterpret_cast<float2*>(out + (size_t)r0 * E + col0)       = o0;
            *reinterpret_cast<float2*>(out + (size_t)(r0 + 8) * E + col0) = o1;
        }
    }
}

// ============================ launch =======================================
extern "C" void kernel_launch(void* const* d_in, const int* in_sizes, int n_in,
                              void* d_out, int out_size)
{
    const float* x  = (const float*)d_in[0];
    const float* Wq = (const float*)d_in[1];
    const float* bq = (const float*)d_in[2];
    const float* Wk = (const float*)d_in[3];
    const float* bk = (const float*)d_in[4];
    const float* Wv = (const float*)d_in[5];
    const float* bv = (const float*)d_in[6];
    const float* Wu = (const float*)d_in[7];
    const float* bu = (const float*)d_in[8];
    float* out = (float*)d_out;

    const int Nrows = in_sizes[0] / E;
    const int tiles = Nrows / TM;   // 1024

    cudaFuncSetAttribute(qkv_softmax_kernel,
                         cudaFuncAttributeMaxDynamicSharedMemorySize, K1_SMEM);
    cudaFuncSetAttribute(unify_gemm_kernel,
                         cudaFuncAttributeMaxDynamicSharedMemorySize, K2_SMEM);

    prep_qkv<<<(H * 3 * S * S + 255) / 256, 256>>>(Wq, Wk, Wv);
    prep_wu<<<(E * E + 255) / 256, 256>>>(Wu);
    qkv_softmax_kernel<<<tiles, 256, K1_SMEM>>>(x, bq, bk, bv);
    unify_gemm_kernel<<<tiles, 256, K2_SMEM>>>(bu, out);
}

// round 5
// speedup vs baseline: 3.5000x; 1.0499x over previous
#include <cuda_runtime.h>
#include <cuda_bf16.h>
#include <cstdint>

// ============================ problem constants ============================
constexpr int E = 512, H = 8, S = 64, TM = 64;

// ============================ device scratch (weights only) ================
// per head: {q_hi, k_hi, v_hi, v_lo} 64x64 bf16 [s][t] SW128 tiles (8KB each) = 32KB/head
__device__ __align__(1024) unsigned char g_wqkv[H * 4 * 8192];
// Wu chunks: it = nh*16 + kc -> {hi[32k x 256n] 16KB, lo 16KB} swz512, 32KB each
__device__ __align__(1024) unsigned char g_wub[32 * 32768];

// ============================ helpers ======================================
__device__ __forceinline__ uint32_t smem_u32(const void* p) {
    uint32_t a;
    asm("{ .reg .u64 t; cvta.to.shared.u64 t, %1; cvt.u32.u64 %0, t; }" : "=r"(a) : "l"(p));
    return a;
}
__host__ __device__ __forceinline__ uint32_t swz128(uint32_t o) { return o ^ ((o >> 3) & 0x70); }
__host__ __device__ __forceinline__ uint32_t swz512(uint32_t o) { return o ^ ((o >> 5) & 0x70); }

__device__ __forceinline__ void ldsm_x4(uint32_t (&r)[4], uint32_t a) {
    asm volatile("ldmatrix.sync.aligned.m8n8.x4.shared.b16 {%0,%1,%2,%3}, [%4];"
        : "=r"(r[0]), "=r"(r[1]), "=r"(r[2]), "=r"(r[3]) : "r"(a));
}
__device__ __forceinline__ void ldsm_x4t(uint32_t (&r)[4], uint32_t a) {
    asm volatile("ldmatrix.sync.aligned.m8n8.x4.trans.shared.b16 {%0,%1,%2,%3}, [%4];"
        : "=r"(r[0]), "=r"(r[1]), "=r"(r[2]), "=r"(r[3]) : "r"(a));
}
__device__ __forceinline__ void mma16816(float (&d)[4], const uint32_t (&a)[4],
                                         uint32_t b0, uint32_t b1) {
    asm volatile("mma.sync.aligned.m16n8k16.row.col.f32.bf16.bf16.f32 "
        "{%0,%1,%2,%3}, {%4,%5,%6,%7}, {%8,%9}, {%0,%1,%2,%3};"
        : "+f"(d[0]), "+f"(d[1]), "+f"(d[2]), "+f"(d[3])
        : "r"(a[0]), "r"(a[1]), "r"(a[2]), "r"(a[3]), "r"(b0), "r"(b1));
}
__device__ __forceinline__ void cp16(uint32_t dst, const void* src) {
    asm volatile("cp.async.cg.shared.global [%0], [%1], 16;" :: "r"(dst), "l"(src));
}
#define CP_COMMIT() asm volatile("cp.async.commit_group;" ::: "memory")
#define CP_WAIT(n)  asm volatile("cp.async.wait_group %0;" :: "n"(n) : "memory")

__device__ __forceinline__ void split2(float x, __nv_bfloat16& hi, __nv_bfloat16& lo) {
    hi = __float2bfloat16(x);
    lo = __float2bfloat16(x - __bfloat162float(hi));
}
__device__ __forceinline__ uint32_t pack2(__nv_bfloat16 a, __nv_bfloat16 b) {
    __nv_bfloat162 p(a, b);
    return *reinterpret_cast<uint32_t*>(&p);
}

// ============================ prep kernels =================================
// mats: 0=q_hi, 1=k_hi, 2=v_hi, 3=v_lo ; tile layout [s-rows][t-cols] SW128
__global__ void prep_qkv(const float* __restrict__ Wq, const float* __restrict__ Wk,
                         const float* __restrict__ Wv) {
    int idx = blockIdx.x * 256 + threadIdx.x;
    if (idx >= H * 4 * S * S) return;
    int h = idx >> 14;
    int mat = (idx >> 12) & 3;
    int s = (idx >> 6) & 63, t = idx & 63;
    const float* W = (mat == 0) ? Wq : ((mat == 1) ? Wk : Wv);
    float v = W[(h * S + s) * S + t];
    __nv_bfloat16 hi, lo; split2(v, hi, lo);
    __nv_bfloat16 val = (mat == 3) ? lo : hi;
    uint32_t off = swz128((uint32_t)(s * 128 + t * 2));
    *reinterpret_cast<__nv_bfloat16*>(g_wqkv + (size_t)(h * 4 + mat) * 8192 + off) = val;
}
__global__ void prep_wu(const float* __restrict__ Wu) {
    int idx = blockIdx.x * 256 + threadIdx.x;
    if (idx >= E * E) return;
    int k = idx >> 9, n = idx & 511;
    float v = Wu[idx];
    __nv_bfloat16 hi, lo; split2(v, hi, lo);
    int kc = k >> 5, kk = k & 31, nh = n >> 8, nn = n & 255;
    size_t base = (size_t)(nh * 16 + kc) * 32768;
    uint32_t off = swz512((uint32_t)(kk * 512 + nn * 2));
    *reinterpret_cast<__nv_bfloat16*>(g_wub + base + off)         = hi;
    *reinterpret_cast<__nv_bfloat16*>(g_wub + base + 16384 + off) = lo;
}

// ============================ fused kernel =================================
// smem map (bytes):
//   sT_hi  @ 0       : 8 tiles [64r x 64k] bf16 SW128, 8KB each (head h -> tile h) = 64KB
//   sT_lo  @ 65536   : same = 64KB
//   sWB    @ 131072  : phase1 = W head-pair {lh0: 4 mats, lh1: 4 mats} 64KB
//                      phase2 = B double buffer 2 x {hi 16KB, lo 16KB} = 64KB
//   sX     @ 196608  : phase1 x stage: [lh][hi/lo] 4 tiles [64x64] SW128 8KB = 32KB
constexpr uint32_t ST_HI = 0, ST_LO = 65536, SWB = 131072, SX = 196608;
constexpr uint32_t SMEM_TOTAL = 229376;

__global__ __launch_bounds__(256, 1)
void fused_sparse_attn(const float* __restrict__ x,
                       const float* __restrict__ bq, const float* __restrict__ bk,
                       const float* __restrict__ bv,
                       const float* __restrict__ bu, float* __restrict__ out)
{
    extern __shared__ unsigned char smem[];
    const uint32_t sb = smem_u32(smem);
    const int tid = threadIdx.x, lane = tid & 31, wid = tid >> 5;
    const int row0 = blockIdx.x * TM;
    const float SC = 0.04419417382415922f;   // 1/sqrt(512)

    const int g  = lane >> 2;                // row in m8 group
    const int qd = lane & 3;                 // quad lane -> col pair
    const uint32_t hiSel = (uint32_t)((lane >> 4) << 4);

    // ===================== Phase 1: QKV + softmax -> sT ====================
    const int lh = wid >> 2;                 // local head (0/1) in pair
    const int wm = wid & 3;                  // m-position (16 rows)
    const uint32_t aRow = (uint32_t)(wm * 16 + (lane & 15));

    for (int hp = 0; hp < 4; ++hp) {
        // -- stage W head-pair (pre-swizzled, 64KB contiguous) --
        {
            const char* src = (const char*)g_wqkv + (size_t)hp * 65536;
            #pragma unroll
            for (int i = 0; i < 16; ++i) {
                uint32_t o = (uint32_t)(tid + i * 256) * 16;
                cp16(sb + SWB + o, src + o);
            }
            CP_COMMIT();
        }
        // -- stage x slice for both heads: 64 rows x 128 cols -> bf16 hi/lo --
        #pragma unroll
        for (int i = 0; i < 8; ++i) {
            int idx = tid + i * 256;               // 2048 float4
            int r = idx >> 5, c4 = idx & 31;       // 32 float4 per row
            float4 xv = *reinterpret_cast<const float4*>(
                x + (size_t)(row0 + r) * E + hp * 128 + c4 * 4);
            __nv_bfloat16 h0,l0,h1,l1,h2,l2,h3,l3;
            split2(xv.x,h0,l0); split2(xv.y,h1,l1); split2(xv.z,h2,l2); split2(xv.w,h3,l3);
            uint32_t base = SX + (uint32_t)(c4 >> 4) * 16384;
            uint32_t off = swz128((uint32_t)(r * 128 + (c4 & 15) * 8));
            *reinterpret_cast<uint2*>(smem + base + off)        = make_uint2(pack2(h0,h1), pack2(h2,h3));
            *reinterpret_cast<uint2*>(smem + base + 8192 + off) = make_uint2(pack2(l0,l1), pack2(l2,l3));
        }
        CP_WAIT(0);
        __syncthreads();

        // -- mma: this warp = head (hp*2+lh), rows wm*16..+15, all 64 cols --
        const int h = hp * 2 + lh;
        float aq[8][4], ak[8][4], av[8][4];
        #pragma unroll
        for (int nt = 0; nt < 8; ++nt)
            #pragma unroll
            for (int c = 0; c < 4; ++c) { aq[nt][c] = 0.f; ak[nt][c] = 0.f; av[nt][c] = 0.f; }

        const uint32_t xbase = sb + SX + (uint32_t)lh * 16384;
        const uint32_t wbase = sb + SWB + (uint32_t)lh * 32768;

        #pragma unroll
        for (int ks = 0; ks < 4; ++ks) {
            uint32_t aHi[4], aLo[4];
            uint32_t aoff = swz128(aRow * 128 + (uint32_t)ks * 32 + hiSel);
            ldsm_x4(aHi, xbase + aoff);
            ldsm_x4(aLo, xbase + 8192 + aoff);
            #pragma unroll
            for (int ntp = 0; ntp < 4; ++ntp) {
                uint32_t boff = swz128((uint32_t)(ks * 16 + (lane & 15)) * 128
                                       + (uint32_t)ntp * 32 + hiSel);
                uint32_t bQ[4], bK[4], bVh[4], bVl[4];
                ldsm_x4t(bQ,  wbase + boff);
                ldsm_x4t(bK,  wbase + 8192  + boff);
                ldsm_x4t(bVh, wbase + 16384 + boff);
                ldsm_x4t(bVl, wbase + 24576 + boff);
                // q: 2-term (x_hi + x_lo) @ Wq_hi
                mma16816(aq[2*ntp],   aHi, bQ[0], bQ[1]);
                mma16816(aq[2*ntp+1], aHi, bQ[2], bQ[3]);
                mma16816(aq[2*ntp],   aLo, bQ[0], bQ[1]);
                mma16816(aq[2*ntp+1], aLo, bQ[2], bQ[3]);
                // k: 2-term
                mma16816(ak[2*ntp],   aHi, bK[0], bK[1]);
                mma16816(ak[2*ntp+1], aHi, bK[2], bK[3]);
                mma16816(ak[2*ntp],   aLo, bK[0], bK[1]);
                mma16816(ak[2*ntp+1], aLo, bK[2], bK[3]);
                // v: 3-term
                mma16816(av[2*ntp],   aHi, bVh[0], bVh[1]);
                mma16816(av[2*ntp+1], aHi, bVh[2], bVh[3]);
                mma16816(av[2*ntp],   aLo, bVh[0], bVh[1]);
                mma16816(av[2*ntp+1], aLo, bVh[2], bVh[3]);
                mma16816(av[2*ntp],   aHi, bVl[0], bVl[1]);
                mma16816(av[2*ntp+1], aHi, bVl[2], bVl[3]);
            }
        }

        // -- softmax (quad-local) + t split -> sT tile h --
        const float* bqh = bq + h * S;
        const float* bkh = bk + h * S;
        const float* bvh = bv + h * S;
        #pragma unroll
        for (int rr = 0; rr < 2; ++rr) {
            float ev[16], vv[16];
            float ssum = 0.f;
            #pragma unroll
            for (int nt = 0; nt < 8; ++nt) {
                int col0 = nt * 8 + qd * 2;
                float2 b1 = *reinterpret_cast<const float2*>(bqh + col0);
                float2 b2 = *reinterpret_cast<const float2*>(bkh + col0);
                float2 b3 = *reinterpret_cast<const float2*>(bvh + col0);
                float q0 = aq[nt][rr*2+0] + b1.x, q1 = aq[nt][rr*2+1] + b1.y;
                float k0 = ak[nt][rr*2+0] + b2.x, k1 = ak[nt][rr*2+1] + b2.y;
                float e0 = __expf(q0 * k0 * SC), e1 = __expf(q1 * k1 * SC);
                ev[nt*2] = e0; ev[nt*2+1] = e1; ssum += e0 + e1;
                vv[nt*2]   = av[nt][rr*2+0] + b3.x;
                vv[nt*2+1] = av[nt][rr*2+1] + b3.y;
            }
            ssum += __shfl_xor_sync(0xffffffffu, ssum, 1);
            ssum += __shfl_xor_sync(0xffffffffu, ssum, 2);
            float inv = 1.0f / ssum;
            int rt = wm * 16 + g + rr * 8;
            #pragma unroll
            for (int nt = 0; nt < 8; ++nt) {
                float t0 = ev[nt*2]   * inv * vv[nt*2];
                float t1 = ev[nt*2+1] * inv * vv[nt*2+1];
                __nv_bfloat16 h0,l0,h1,l1;
                split2(t0,h0,l0); split2(t1,h1,l1);
                uint32_t off = (uint32_t)h * 8192
                             + swz128((uint32_t)(rt * 128 + (nt * 8 + qd * 2) * 2));
                *reinterpret_cast<uint32_t*>(smem + ST_HI + off) = pack2(h0, h1);
                *reinterpret_cast<uint32_t*>(smem + ST_LO + off) = pack2(l0, l1);
            }
        }
        __syncthreads();   // sW/sX reuse for next head-pair; sT ready after last
    }

    // ===================== Phase 2: out = t @ Wu + bu ======================
    // warp grid 4m x 2n: rows wm*16, cols (wid>>2)*128 within the nh 256-half
    const int wn = wid >> 2;

    auto load_chunk = [&](int it, int buf) {
        const char* src = (const char*)g_wub + (size_t)it * 32768;
        uint32_t d = sb + SWB + (uint32_t)buf * 32768;
        #pragma unroll
        for (int i = 0; i < 8; ++i) {
            uint32_t o = (uint32_t)(tid + i * 256) * 16;
            cp16(d + o, src + o);
        }
    };

    load_chunk(0, 0);
    CP_COMMIT();

    for (int nh = 0; nh < 2; ++nh) {
        float acc[16][4];
        #pragma unroll
        for (int nt = 0; nt < 16; ++nt)
            #pragma unroll
            for (int c = 0; c < 4; ++c) acc[nt][c] = 0.f;

        for (int kc = 0; kc < 16; ++kc) {
            int it = nh * 16 + kc;
            if (it + 1 < 32) { load_chunk(it + 1, (it + 1) & 1); CP_COMMIT(); CP_WAIT(1); }
            else             { CP_WAIT(0); }
            __syncthreads();

            uint32_t bbase = sb + SWB + (uint32_t)(it & 1) * 32768;
            uint32_t tHi = sb + ST_HI + (uint32_t)(kc >> 1) * 8192;
            uint32_t tLo = sb + ST_LO + (uint32_t)(kc >> 1) * 8192;
            #pragma unroll
            for (int ksg = 0; ksg < 2; ++ksg) {
                uint32_t aHi[4], aLo[4];
                uint32_t aoff = swz128(aRow * 128 + (uint32_t)((kc & 1) * 64 + ksg * 32) + hiSel);
                ldsm_x4(aHi, tHi + aoff);
                ldsm_x4(aLo, tLo + aoff);
                #pragma unroll
                for (int ntp = 0; ntp < 8; ++ntp) {
                    uint32_t boff = swz512((uint32_t)(ksg * 16 + (lane & 15)) * 512
                                           + (uint32_t)(wn * 256 + ntp * 32) + hiSel);
                    uint32_t bHi[4], bLo[4];
                    ldsm_x4t(bHi, bbase + boff);
                    ldsm_x4t(bLo, bbase + 16384 + boff);
                    mma16816(acc[2*ntp],   aHi, bHi[0], bHi[1]);
                    mma16816(acc[2*ntp+1], aHi, bHi[2], bHi[3]);
                    mma16816(acc[2*ntp],   aLo, bHi[0], bHi[1]);
                    mma16816(acc[2*ntp+1], aLo, bHi[2], bHi[3]);
                    mma16816(acc[2*ntp],   aHi, bLo[0], bLo[1]);
                    mma16816(acc[2*ntp+1], aHi, bLo[2], bLo[3]);
                }
            }
            __syncthreads();
        }

        // epilogue for this N-half
        #pragma unroll
        for (int nt = 0; nt < 16; ++nt) {
            int col0 = nh * 256 + wn * 128 + nt * 8 + qd * 2;
            float2 bb = *reinterpret_cast<const float2*>(bu + col0);
            int r0 = row0 + wm * 16 + g;
            float2 o0 = make_float2(acc[nt][0] + bb.x, acc[nt][1] + bb.y);
            float2 o1 = make_float2(acc[nt][2] + bb.x, acc[nt][3] + bb.y);
            *reinterpret_cast<float2*>(out + (size_t)r0 * E + col0)       = o0;
            *reinterpret_cast<float2*>(out + (size_t)(r0 + 8) * E + col0) = o1;
        }
    }
}

// ============================ launch =======================================
extern "C" void kernel_launch(void* const* d_in, const int* in_sizes, int n_in,
                              void* d_out, int out_size)
{
    const float* x  = (const float*)d_in[0];
    const float* Wq = (const float*)d_in[1];
    const float* bq = (const float*)d_in[2];
    const float* Wk = (const float*)d_in[3];
    const float* bk = (const float*)d_in[4];
    const float* Wv = (const float*)d_in[5];
    const float* bv = (const float*)d_in[6];
    const float* Wu = (const float*)d_in[7];
    const float* bu = (const float*)d_in[8];
    float* out = (float*)d_out;

    const int Nrows = in_sizes[0] / E;
    const int tiles = Nrows / TM;   // 2048

    cudaFuncSetAttribute(fused_sparse_attn,
                         cudaFuncAttributeMaxDynamicSharedMemorySize, SMEM_TOTAL);

    prep_qkv<<<(H * 4 * S * S + 255) / 256, 256>>>(Wq, Wk, Wv);
    prep_wu<<<(E * E + 255) / 256, 256>>>(Wu);
    fused_sparse_attn<<<tiles, 256, SMEM_TOTAL>>>(x, bq, bk, bv, bu, out);
}

// round 6
// speedup vs baseline: 4.0215x; 1.1490x over previous
#include <cuda_runtime.h>
#include <cuda_fp16.h>
#include <cstdint>

// ============================ problem constants ============================
constexpr int E = 512, H = 8, S = 64, TM = 64;

// ============================ device scratch (weights only) ================
// per head: {q_hi, k_hi, v_hi} 64x64 fp16 [s][t] SW128 tiles (8KB each) = 24KB/head
__device__ __align__(1024) unsigned char g_wqkv[H * 3 * 8192];
// Wu_hi chunks: bidx = nh*8 + kc -> [64k x 256n] fp16 swz512, 32KB each (512KB total)
__device__ __align__(1024) unsigned char g_wub[16 * 32768];

// ============================ helpers ======================================
__device__ __forceinline__ uint32_t smem_u32(const void* p) {
    uint32_t a;
    asm("{ .reg .u64 t; cvta.to.shared.u64 t, %1; cvt.u32.u64 %0, t; }" : "=r"(a) : "l"(p));
    return a;
}
__host__ __device__ __forceinline__ uint32_t swz128(uint32_t o) { return o ^ ((o >> 3) & 0x70); }
__host__ __device__ __forceinline__ uint32_t swz512(uint32_t o) { return o ^ ((o >> 5) & 0x70); }

__device__ __forceinline__ void ldsm_x4(uint32_t (&r)[4], uint32_t a) {
    asm volatile("ldmatrix.sync.aligned.m8n8.x4.shared.b16 {%0,%1,%2,%3}, [%4];"
        : "=r"(r[0]), "=r"(r[1]), "=r"(r[2]), "=r"(r[3]) : "r"(a));
}
__device__ __forceinline__ void ldsm_x4t(uint32_t (&r)[4], uint32_t a) {
    asm volatile("ldmatrix.sync.aligned.m8n8.x4.trans.shared.b16 {%0,%1,%2,%3}, [%4];"
        : "=r"(r[0]), "=r"(r[1]), "=r"(r[2]), "=r"(r[3]) : "r"(a));
}
__device__ __forceinline__ void mma16816(float (&d)[4], const uint32_t (&a)[4],
                                         uint32_t b0, uint32_t b1) {
    asm volatile("mma.sync.aligned.m16n8k16.row.col.f32.f16.f16.f32 "
        "{%0,%1,%2,%3}, {%4,%5,%6,%7}, {%8,%9}, {%0,%1,%2,%3};"
        : "+f"(d[0]), "+f"(d[1]), "+f"(d[2]), "+f"(d[3])
        : "r"(a[0]), "r"(a[1]), "r"(a[2]), "r"(a[3]), "r"(b0), "r"(b1));
}
__device__ __forceinline__ void cp16(uint32_t dst, const void* src) {
    asm volatile("cp.async.cg.shared.global [%0], [%1], 16;" :: "r"(dst), "l"(src));
}
#define CP_COMMIT() asm volatile("cp.async.commit_group;" ::: "memory")
#define CP_WAIT(n)  asm volatile("cp.async.wait_group %0;" :: "n"(n) : "memory")

__device__ __forceinline__ void split2h(float x, __half& hi, __half& lo) {
    hi = __float2half(x);
    lo = __float2half(x - __half2float(hi));
}
__device__ __forceinline__ uint32_t pack2h(__half a, __half b) {
    __half2 p(a, b);
    return *reinterpret_cast<uint32_t*>(&p);
}

// ============================ prep kernels =================================
// mats: 0=q_hi, 1=k_hi, 2=v_hi ; tile layout [s-rows][t-cols] fp16 SW128
__global__ void prep_qkv(const float* __restrict__ Wq, const float* __restrict__ Wk,
                         const float* __restrict__ Wv) {
    int idx = blockIdx.x * 256 + threadIdx.x;
    if (idx >= H * 3 * S * S) return;
    int h = idx / (3 * S * S);
    int mat = (idx >> 12) % 3;
    int s = (idx >> 6) & 63, t = idx & 63;
    const float* W = (mat == 0) ? Wq : ((mat == 1) ? Wk : Wv);
    float v = W[(h * S + s) * S + t];
    uint32_t off = swz128((uint32_t)(s * 128 + t * 2));
    *reinterpret_cast<__half*>(g_wqkv + (size_t)(h * 3 + mat) * 8192 + off) = __float2half(v);
}
// Wu_hi: chunk bidx = (n>>8)*8 + (k>>6): [64k x 256n] fp16 swz512
__global__ void prep_wu(const float* __restrict__ Wu) {
    int idx = blockIdx.x * 256 + threadIdx.x;
    if (idx >= E * E) return;
    int k = idx >> 9, n = idx & 511;
    int kc = k >> 6, kk = k & 63, nh = n >> 8, nn = n & 255;
    size_t base = (size_t)(nh * 8 + kc) * 32768;
    uint32_t off = swz512((uint32_t)(kk * 512 + nn * 2));
    *reinterpret_cast<__half*>(g_wub + base + off) = __float2half(Wu[idx]);
}

// ============================ fused kernel =================================
// smem map (bytes):
//   sT_hi @ 0      : 8 tiles [64r x 64k] fp16 SW128, 8KB each (head h = k-chunk h) = 64KB
//   sT_lo @ 65536  : same, values scaled x512 = 64KB
//   sWB   @ 131072 : phase1 = W head-pair {lh0:3 mats, lh1:3 mats} 48KB
//                    phase2 = B double buffer 2 x 32KB = 64KB
//   sX    @ 196608 : phase1 x stage: [lh][hi/lo] tiles [64x64] fp16 SW128 = 32KB
constexpr uint32_t ST_HI = 0, ST_LO = 65536, SWB = 131072, SX = 196608;
constexpr uint32_t SMEM_TOTAL = 229376;

__global__ __launch_bounds__(256, 1)
void fused_sparse_attn(const float* __restrict__ x,
                       const float* __restrict__ bq, const float* __restrict__ bk,
                       const float* __restrict__ bv,
                       const float* __restrict__ bu, float* __restrict__ out)
{
    extern __shared__ unsigned char smem[];
    const uint32_t sb = smem_u32(smem);
    const int tid = threadIdx.x, lane = tid & 31, wid = tid >> 5;
    const int row0 = blockIdx.x * TM;
    const float SC = 0.04419417382415922f;   // 1/sqrt(512)

    const int g  = lane >> 2;
    const int qd = lane & 3;
    const uint32_t hiSel = (uint32_t)((lane >> 4) << 4);

    // ===================== Phase 1: QKV + softmax -> sT ====================
    const int lh = wid >> 2;                  // local head in pair
    const int wm = wid & 3;                   // 16-row m position
    const uint32_t aRow = (uint32_t)(wm * 16 + (lane & 15));

    for (int hp = 0; hp < 4; ++hp) {
        // -- stage W head-pair (pre-swizzled, 48KB contiguous) --
        {
            const char* src = (const char*)g_wqkv + (size_t)hp * 49152;
            #pragma unroll
            for (int i = 0; i < 12; ++i) {
                uint32_t o = (uint32_t)(tid + i * 256) * 16;
                cp16(sb + SWB + o, src + o);
            }
            CP_COMMIT();
        }
        // -- stage x slice for both heads: 64 rows x 128 cols -> fp16 hi/lo --
        #pragma unroll
        for (int i = 0; i < 8; ++i) {
            int idx = tid + i * 256;
            int r = idx >> 5, c4 = idx & 31;
            float4 xv = *reinterpret_cast<const float4*>(
                x + (size_t)(row0 + r) * E + hp * 128 + c4 * 4);
            __half h0,l0,h1,l1,h2,l2,h3,l3;
            split2h(xv.x,h0,l0); split2h(xv.y,h1,l1); split2h(xv.z,h2,l2); split2h(xv.w,h3,l3);
            uint32_t base = SX + (uint32_t)(c4 >> 4) * 16384;
            uint32_t off = swz128((uint32_t)(r * 128 + (c4 & 15) * 8));
            *reinterpret_cast<uint2*>(smem + base + off)        = make_uint2(pack2h(h0,h1), pack2h(h2,h3));
            *reinterpret_cast<uint2*>(smem + base + 8192 + off) = make_uint2(pack2h(l0,l1), pack2h(l2,l3));
        }
        CP_WAIT(0);
        __syncthreads();

        // -- mma: this warp = head hp*2+lh, rows wm*16..+15, all 64 cols --
        const int h = hp * 2 + lh;
        float aq[8][4], ak[8][4], av[8][4];
        #pragma unroll
        for (int nt = 0; nt < 8; ++nt)
            #pragma unroll
            for (int c = 0; c < 4; ++c) { aq[nt][c] = 0.f; ak[nt][c] = 0.f; av[nt][c] = 0.f; }

        const uint32_t xbase = sb + SX + (uint32_t)lh * 16384;
        const uint32_t wbase = sb + SWB + (uint32_t)lh * 24576;

        #pragma unroll
        for (int ks = 0; ks < 4; ++ks) {
            uint32_t aHi[4], aLo[4];
            uint32_t aoff = swz128(aRow * 128 + (uint32_t)ks * 32 + hiSel);
            ldsm_x4(aHi, xbase + aoff);
            ldsm_x4(aLo, xbase + 8192 + aoff);
            #pragma unroll
            for (int ntp = 0; ntp < 4; ++ntp) {
                uint32_t boff = swz128((uint32_t)(ks * 16 + (lane & 15)) * 128
                                       + (uint32_t)ntp * 32 + hiSel);
                uint32_t bQ[4], bK[4], bV[4];
                ldsm_x4t(bQ, wbase + boff);
                ldsm_x4t(bK, wbase + 8192  + boff);
                ldsm_x4t(bV, wbase + 16384 + boff);
                // q, k: 1-pass (x_hi only) — softmax-damped error
                mma16816(aq[2*ntp],   aHi, bQ[0], bQ[1]);
                mma16816(aq[2*ntp+1], aHi, bQ[2], bQ[3]);
                mma16816(ak[2*ntp],   aHi, bK[0], bK[1]);
                mma16816(ak[2*ntp+1], aHi, bK[2], bK[3]);
                // v: 2-pass (x_hi + x_lo)
                mma16816(av[2*ntp],   aHi, bV[0], bV[1]);
                mma16816(av[2*ntp+1], aHi, bV[2], bV[3]);
                mma16816(av[2*ntp],   aLo, bV[0], bV[1]);
                mma16816(av[2*ntp+1], aLo, bV[2], bV[3]);
            }
        }

        // -- softmax (quad-local) + t split -> sT tile h (lo scaled x512) --
        const float* bqh = bq + h * S;
        const float* bkh = bk + h * S;
        const float* bvh = bv + h * S;
        #pragma unroll
        for (int rr = 0; rr < 2; ++rr) {
            float ev[16], vv[16];
            float ssum = 0.f;
            #pragma unroll
            for (int nt = 0; nt < 8; ++nt) {
                int col0 = nt * 8 + qd * 2;
                float2 b1 = *reinterpret_cast<const float2*>(bqh + col0);
                float2 b2 = *reinterpret_cast<const float2*>(bkh + col0);
                float2 b3 = *reinterpret_cast<const float2*>(bvh + col0);
                float q0 = aq[nt][rr*2+0] + b1.x, q1 = aq[nt][rr*2+1] + b1.y;
                float k0 = ak[nt][rr*2+0] + b2.x, k1 = ak[nt][rr*2+1] + b2.y;
                float e0 = __expf(q0 * k0 * SC), e1 = __expf(q1 * k1 * SC);
                ev[nt*2] = e0; ev[nt*2+1] = e1; ssum += e0 + e1;
                vv[nt*2]   = av[nt][rr*2+0] + b3.x;
                vv[nt*2+1] = av[nt][rr*2+1] + b3.y;
            }
            ssum += __shfl_xor_sync(0xffffffffu, ssum, 1);
            ssum += __shfl_xor_sync(0xffffffffu, ssum, 2);
            float inv = 1.0f / ssum;
            int rt = wm * 16 + g + rr * 8;
            #pragma unroll
            for (int nt = 0; nt < 8; ++nt) {
                float t0 = ev[nt*2]   * inv * vv[nt*2];
                float t1 = ev[nt*2+1] * inv * vv[nt*2+1];
                __half h0 = __float2half(t0);
                __half h1 = __float2half(t1);
                __half l0 = __float2half((t0 - __half2float(h0)) * 512.0f);
                __half l1 = __float2half((t1 - __half2float(h1)) * 512.0f);
                uint32_t off = (uint32_t)h * 8192
                             + swz128((uint32_t)(rt * 128 + (nt * 8 + qd * 2) * 2));
                *reinterpret_cast<uint32_t*>(smem + ST_HI + off) = pack2h(h0, h1);
                *reinterpret_cast<uint32_t*>(smem + ST_LO + off) = pack2h(l0, l1);
            }
        }
        __syncthreads();   // sWB/sX reuse next head-pair
    }

    // ===================== Phase 2: out = t @ Wu_hi + bu ===================
    // per n-half: acc = (Σ_k t_lo' @ W) * 2^-9 + Σ_k t_hi @ W
    const int wn = wid >> 2;   // n position (2 x 128 cols within the 256 half)

    auto load_B = [&](int bidx, int buf) {
        const char* src = (const char*)g_wub + (size_t)bidx * 32768;
        uint32_t d = sb + SWB + (uint32_t)buf * 32768;
        #pragma unroll
        for (int i = 0; i < 8; ++i) {
            uint32_t o = (uint32_t)(tid + i * 256) * 16;
            cp16(d + o, src + o);
        }
    };

    load_B(0, 0);
    CP_COMMIT();

    for (int nh = 0; nh < 2; ++nh) {
        float acc[16][4];
        #pragma unroll
        for (int nt = 0; nt < 16; ++nt)
            #pragma unroll
            for (int c = 0; c < 4; ++c) acc[nt][c] = 0.f;

        #pragma unroll
        for (int pass = 0; pass < 2; ++pass) {         // 0 = lo(scaled), 1 = hi
            for (int kc = 0; kc < 8; ++kc) {
                int s = nh * 16 + pass * 8 + kc;       // global step 0..31
                CP_WAIT(0);
                __syncthreads();
                if (s + 1 < 32) {
                    int sn = s + 1;
                    load_B(((sn >> 4) * 8) + (sn & 7), sn & 1);
                    CP_COMMIT();
                }
                uint32_t bbase = sb + SWB + (uint32_t)(s & 1) * 32768;
                uint32_t tA = sb + (pass ? ST_HI : ST_LO) + (uint32_t)kc * 8192;
                #pragma unroll
                for (int ksg = 0; ksg < 4; ++ksg) {
                    uint32_t a[4];
                    ldsm_x4(a, tA + swz128(aRow * 128 + (uint32_t)ksg * 32 + hiSel));
                    #pragma unroll
                    for (int ntp = 0; ntp < 8; ++ntp) {
                        uint32_t boff = swz512((uint32_t)(ksg * 16 + (lane & 15)) * 512
                                               + (uint32_t)(wn * 256 + ntp * 32) + hiSel);
                        uint32_t b[4];
                        ldsm_x4t(b, bbase + boff);
                        mma16816(acc[2*ntp],   a, b[0], b[1]);
                        mma16816(acc[2*ntp+1], a, b[2], b[3]);
                    }
                }
            }
            if (pass == 0) {
                const float ds = 1.0f / 512.0f;
                #pragma unroll
                for (int nt = 0; nt < 16; ++nt)
                    #pragma unroll
                    for (int c = 0; c < 4; ++c) acc[nt][c] *= ds;
            }
        }

        // epilogue for this N-half
        #pragma unroll
        for (int nt = 0; nt < 16; ++nt) {
            int col0 = nh * 256 + wn * 128 + nt * 8 + qd * 2;
            float2 bb = *reinterpret_cast<const float2*>(bu + col0);
            int r0 = row0 + wm * 16 + g;
            float2 o0 = make_float2(acc[nt][0] + bb.x, acc[nt][1] + bb.y);
            float2 o1 = make_float2(acc[nt][2] + bb.x, acc[nt][3] + bb.y);
            *reinterpret_cast<float2*>(out + (size_t)r0 * E + col0)       = o0;
            *reinterpret_cast<float2*>(out + (size_t)(r0 + 8) * E + col0) = o1;
        }
    }
}

// ============================ launch =======================================
extern "C" void kernel_launch(void* const* d_in, const int* in_sizes, int n_in,
                              void* d_out, int out_size)
{
    const float* x  = (const float*)d_in[0];
    const float* Wq = (const float*)d_in[1];
    const float* bq = (const float*)d_in[2];
    const float* Wk = (const float*)d_in[3];
    const float* bk = (const float*)d_in[4];
    const float* Wv = (const float*)d_in[5];
    const float* bv = (const float*)d_in[6];
    const float* Wu = (const float*)d_in[7];
    const float* bu = (const float*)d_in[8];
    float* out = (float*)d_out;

    const int Nrows = in_sizes[0] / E;
    const int tiles = Nrows / TM;   // 2048

    cudaFuncSetAttribute(fused_sparse_attn,
                         cudaFuncAttributeMaxDynamicSharedMemorySize, SMEM_TOTAL);

    prep_qkv<<<(H * 3 * S * S + 255) / 256, 256>>>(Wq, Wk, Wv);
    prep_wu<<<(E * E + 255) / 256, 256>>>(Wu);
    fused_sparse_attn<<<tiles, 256, SMEM_TOTAL>>>(x, bq, bk, bv, bu, out);
}

// round 7
// speedup vs baseline: 6.7317x; 1.6739x over previous
#include <cuda_runtime.h>
#include <cuda_fp16.h>
#include <cstdint>

// ============================ problem constants ============================
constexpr int E = 512, H = 8, S = 64, TM = 64;

// ============================ device scratch (weights only) ================
// per head: {q_hi, k_hi, v_hi} 64x64 fp16 [s][t] SW128 tiles (8KB each) = 24KB/head
__device__ __align__(1024) unsigned char g_wqkv[H * 3 * 8192];
// Wu_hi chunks: bidx = nh*8 + kc -> [64k x 256n] fp16 swz512, 32KB each (512KB total)
__device__ __align__(1024) unsigned char g_wub[16 * 32768];

// ============================ helpers ======================================
__device__ __forceinline__ uint32_t smem_u32(const void* p) {
    uint32_t a;
    asm("{ .reg .u64 t; cvta.to.shared.u64 t, %1; cvt.u32.u64 %0, t; }" : "=r"(a) : "l"(p));
    return a;
}
__host__ __device__ __forceinline__ uint32_t swz128(uint32_t o) { return o ^ ((o >> 3) & 0x70); }
__host__ __device__ __forceinline__ uint32_t swz512(uint32_t o) { return o ^ ((o >> 5) & 0x70); }

__device__ __forceinline__ void ldsm_x4(uint32_t (&r)[4], uint32_t a) {
    asm volatile("ldmatrix.sync.aligned.m8n8.x4.shared.b16 {%0,%1,%2,%3}, [%4];"
        : "=r"(r[0]), "=r"(r[1]), "=r"(r[2]), "=r"(r[3]) : "r"(a));
}
__device__ __forceinline__ void ldsm_x4t(uint32_t (&r)[4], uint32_t a) {
    asm volatile("ldmatrix.sync.aligned.m8n8.x4.trans.shared.b16 {%0,%1,%2,%3}, [%4];"
        : "=r"(r[0]), "=r"(r[1]), "=r"(r[2]), "=r"(r[3]) : "r"(a));
}
__device__ __forceinline__ void mma16816(float (&d)[4], const uint32_t (&a)[4],
                                         uint32_t b0, uint32_t b1) {
    asm volatile("mma.sync.aligned.m16n8k16.row.col.f32.f16.f16.f32 "
        "{%0,%1,%2,%3}, {%4,%5,%6,%7}, {%8,%9}, {%0,%1,%2,%3};"
        : "+f"(d[0]), "+f"(d[1]), "+f"(d[2]), "+f"(d[3])
        : "r"(a[0]), "r"(a[1]), "r"(a[2]), "r"(a[3]), "r"(b0), "r"(b1));
}
__device__ __forceinline__ void cp16(uint32_t dst, const void* src) {
    asm volatile("cp.async.cg.shared.global [%0], [%1], 16;" :: "r"(dst), "l"(src));
}
#define CP_COMMIT() asm volatile("cp.async.commit_group;" ::: "memory")
#define CP_WAIT(n)  asm volatile("cp.async.wait_group %0;" :: "n"(n) : "memory")

__device__ __forceinline__ void split2h(float x, __half& hi, __half& lo) {
    hi = __float2half(x);
    lo = __float2half(x - __half2float(hi));
}
__device__ __forceinline__ uint32_t pack2h(__half a, __half b) {
    __half2 p(a, b);
    return *reinterpret_cast<uint32_t*>(&p);
}

// ============================ prep kernels =================================
// mats: 0=q_hi, 1=k_hi, 2=v_hi ; tile layout [s-rows][t-cols] fp16 SW128
__global__ void prep_qkv(const float* __restrict__ Wq, const float* __restrict__ Wk,
                         const float* __restrict__ Wv) {
    int idx = blockIdx.x * 256 + threadIdx.x;
    if (idx >= H * 3 * S * S) return;
    int h = idx / (3 * S * S);
    int mat = (idx >> 12) % 3;
    int s = (idx >> 6) & 63, t = idx & 63;
    const float* W = (mat == 0) ? Wq : ((mat == 1) ? Wk : Wv);
    float v = W[(h * S + s) * S + t];
    uint32_t off = swz128((uint32_t)(s * 128 + t * 2));
    *reinterpret_cast<__half*>(g_wqkv + (size_t)(h * 3 + mat) * 8192 + off) = __float2half(v);
}
// Wu_hi: chunk bidx = (n>>8)*8 + (k>>6): [64k x 256n] fp16 swz512
__global__ void prep_wu(const float* __restrict__ Wu) {
    int idx = blockIdx.x * 256 + threadIdx.x;
    if (idx >= E * E) return;
    int k = idx >> 9, n = idx & 511;
    int kc = k >> 6, kk = k & 63, nh = n >> 8, nn = n & 255;
    size_t base = (size_t)(nh * 8 + kc) * 32768;
    uint32_t off = swz512((uint32_t)(kk * 512 + nn * 2));
    *reinterpret_cast<__half*>(g_wub + base + off) = __float2half(Wu[idx]);
}

// ============================ fused kernel =================================
// smem map (bytes):
//   sT_hi @ 0      : 8 tiles [64r x 64k] fp16 SW128, 8KB each (head h = k-chunk h) = 64KB
//   sWB   @ 65536  : phase1 = W head-pair {lh0:3 mats, lh1:3 mats} 48KB
//                    phase2 = B double buffer 2 x 32KB = 64KB
//   sX    @ 131072 : phase1 x stage: [lh][hi/lo] tiles [64x64] fp16 SW128 = 32KB
constexpr uint32_t ST_HI = 0, SWB = 65536, SX = 131072;
constexpr uint32_t SMEM_TOTAL = 163840;

__global__ __launch_bounds__(256, 1)
void fused_sparse_attn(const float* __restrict__ x,
                       const float* __restrict__ bq, const float* __restrict__ bk,
                       const float* __restrict__ bv,
                       const float* __restrict__ bu, float* __restrict__ out)
{
    extern __shared__ unsigned char smem[];
    const uint32_t sb = smem_u32(smem);
    const int tid = threadIdx.x, lane = tid & 31, wid = tid >> 5;
    const int row0 = blockIdx.x * TM;
    const float SC = 0.04419417382415922f;   // 1/sqrt(512)

    const int g  = lane >> 2;
    const int qd = lane & 3;
    const uint32_t hiSel = (uint32_t)((lane >> 4) << 4);

    // ===================== Phase 1: QKV + softmax -> sT_hi =================
    const int lh = wid >> 2;                  // local head in pair
    const int wm = wid & 3;                   // 16-row m position
    const uint32_t aRow = (uint32_t)(wm * 16 + (lane & 15));

    for (int hp = 0; hp < 4; ++hp) {
        // -- stage W head-pair (pre-swizzled, 48KB contiguous) --
        {
            const char* src = (const char*)g_wqkv + (size_t)hp * 49152;
            #pragma unroll
            for (int i = 0; i < 12; ++i) {
                uint32_t o = (uint32_t)(tid + i * 256) * 16;
                cp16(sb + SWB + o, src + o);
            }
            CP_COMMIT();
        }
        // -- stage x slice for both heads: 64 rows x 128 cols -> fp16 hi/lo --
        #pragma unroll
        for (int i = 0; i < 8; ++i) {
            int idx = tid + i * 256;
            int r = idx >> 5, c4 = idx & 31;
            float4 xv = *reinterpret_cast<const float4*>(
                x + (size_t)(row0 + r) * E + hp * 128 + c4 * 4);
            __half h0,l0,h1,l1,h2,l2,h3,l3;
            split2h(xv.x,h0,l0); split2h(xv.y,h1,l1); split2h(xv.z,h2,l2); split2h(xv.w,h3,l3);
            uint32_t base = SX + (uint32_t)(c4 >> 4) * 16384;
            uint32_t off = swz128((uint32_t)(r * 128 + (c4 & 15) * 8));
            *reinterpret_cast<uint2*>(smem + base + off)        = make_uint2(pack2h(h0,h1), pack2h(h2,h3));
            *reinterpret_cast<uint2*>(smem + base + 8192 + off) = make_uint2(pack2h(l0,l1), pack2h(l2,l3));
        }
        CP_WAIT(0);
        __syncthreads();

        // -- mma: this warp = head hp*2+lh, rows wm*16..+15, all 64 cols --
        const int h = hp * 2 + lh;
        float aq[8][4], ak[8][4], av[8][4];
        #pragma unroll
        for (int nt = 0; nt < 8; ++nt)
            #pragma unroll
            for (int c = 0; c < 4; ++c) { aq[nt][c] = 0.f; ak[nt][c] = 0.f; av[nt][c] = 0.f; }

        const uint32_t xbase = sb + SX + (uint32_t)lh * 16384;
        const uint32_t wbase = sb + SWB + (uint32_t)lh * 24576;

        #pragma unroll
        for (int ks = 0; ks < 4; ++ks) {
            uint32_t aHi[4], aLo[4];
            uint32_t aoff = swz128(aRow * 128 + (uint32_t)ks * 32 + hiSel);
            ldsm_x4(aHi, xbase + aoff);
            ldsm_x4(aLo, xbase + 8192 + aoff);
            #pragma unroll
            for (int ntp = 0; ntp < 4; ++ntp) {
                uint32_t boff = swz128((uint32_t)(ks * 16 + (lane & 15)) * 128
                                       + (uint32_t)ntp * 32 + hiSel);
                uint32_t bQ[4], bK[4], bV[4];
                ldsm_x4t(bQ, wbase + boff);
                ldsm_x4t(bK, wbase + 8192  + boff);
                ldsm_x4t(bV, wbase + 16384 + boff);
                // q, k: 1-pass (x_hi only) — softmax-damped error
                mma16816(aq[2*ntp],   aHi, bQ[0], bQ[1]);
                mma16816(aq[2*ntp+1], aHi, bQ[2], bQ[3]);
                mma16816(ak[2*ntp],   aHi, bK[0], bK[1]);
                mma16816(ak[2*ntp+1], aHi, bK[2], bK[3]);
                // v: 2-pass (x_hi + x_lo)
                mma16816(av[2*ntp],   aHi, bV[0], bV[1]);
                mma16816(av[2*ntp+1], aHi, bV[2], bV[3]);
                mma16816(av[2*ntp],   aLo, bV[0], bV[1]);
                mma16816(av[2*ntp+1], aLo, bV[2], bV[3]);
            }
        }

        // -- softmax (quad-local) + t -> sT_hi tile h --
        const float* bqh = bq + h * S;
        const float* bkh = bk + h * S;
        const float* bvh = bv + h * S;
        #pragma unroll
        for (int rr = 0; rr < 2; ++rr) {
            float ev[16], vv[16];
            float ssum = 0.f;
            #pragma unroll
            for (int nt = 0; nt < 8; ++nt) {
                int col0 = nt * 8 + qd * 2;
                float2 b1 = *reinterpret_cast<const float2*>(bqh + col0);
                float2 b2 = *reinterpret_cast<const float2*>(bkh + col0);
                float2 b3 = *reinterpret_cast<const float2*>(bvh + col0);
                float q0 = aq[nt][rr*2+0] + b1.x, q1 = aq[nt][rr*2+1] + b1.y;
                float k0 = ak[nt][rr*2+0] + b2.x, k1 = ak[nt][rr*2+1] + b2.y;
                float e0 = __expf(q0 * k0 * SC), e1 = __expf(q1 * k1 * SC);
                ev[nt*2] = e0; ev[nt*2+1] = e1; ssum += e0 + e1;
                vv[nt*2]   = av[nt][rr*2+0] + b3.x;
                vv[nt*2+1] = av[nt][rr*2+1] + b3.y;
            }
            ssum += __shfl_xor_sync(0xffffffffu, ssum, 1);
            ssum += __shfl_xor_sync(0xffffffffu, ssum, 2);
            float inv = 1.0f / ssum;
            int rt = wm * 16 + g + rr * 8;
            #pragma unroll
            for (int nt = 0; nt < 8; ++nt) {
                float t0 = ev[nt*2]   * inv * vv[nt*2];
                float t1 = ev[nt*2+1] * inv * vv[nt*2+1];
                uint32_t off = (uint32_t)h * 8192
                             + swz128((uint32_t)(rt * 128 + (nt * 8 + qd * 2) * 2));
                *reinterpret_cast<uint32_t*>(smem + ST_HI + off) =
                    pack2h(__float2half(t0), __float2half(t1));
            }
        }
        __syncthreads();   // sWB/sX reuse next head-pair
    }

    // ===================== Phase 2: out = t_hi @ Wu_hi + bu ================
    // warp grid 2m x 4n within each 256-col half: warp = 32 rows x 64 cols
    const int pm = wid & 1;        // rows pm*32 .. +31 (2 m16 frags)
    const int pn = wid >> 1;       // cols pn*64 within the 256-half

    auto load_B = [&](int bidx, int buf) {
        const char* src = (const char*)g_wub + (size_t)bidx * 32768;
        uint32_t d = sb + SWB + (uint32_t)buf * 32768;
        #pragma unroll
        for (int i = 0; i < 8; ++i) {
            uint32_t o = (uint32_t)(tid + i * 256) * 16;
            cp16(d + o, src + o);
        }
    };

    load_B(0, 0);
    CP_COMMIT();

    for (int nh = 0; nh < 2; ++nh) {
        float acc[16][4];
        #pragma unroll
        for (int nt = 0; nt < 16; ++nt)
            #pragma unroll
            for (int c = 0; c < 4; ++c) acc[nt][c] = 0.f;

        for (int kc = 0; kc < 8; ++kc) {
            int s = nh * 8 + kc;
            CP_WAIT(0);
            __syncthreads();
            if (s + 1 < 16) { load_B(s + 1, (s + 1) & 1); CP_COMMIT(); }

            uint32_t bbase = sb + SWB + (uint32_t)(s & 1) * 32768;
            uint32_t tA = sb + ST_HI + (uint32_t)kc * 8192;
            #pragma unroll
            for (int ksg = 0; ksg < 4; ++ksg) {
                uint32_t a0[4], a1[4];
                uint32_t kOff = (uint32_t)ksg * 32 + hiSel;
                ldsm_x4(a0, tA + swz128((uint32_t)(pm * 32 + (lane & 15)) * 128 + kOff));
                ldsm_x4(a1, tA + swz128((uint32_t)(pm * 32 + 16 + (lane & 15)) * 128 + kOff));
                #pragma unroll
                for (int ntp = 0; ntp < 4; ++ntp) {
                    uint32_t boff = swz512((uint32_t)(ksg * 16 + (lane & 15)) * 512
                                           + (uint32_t)(pn * 128 + ntp * 32) + hiSel);
                    uint32_t b[4];
                    ldsm_x4t(b, bbase + boff);
                    mma16816(acc[2*ntp],     a0, b[0], b[1]);
                    mma16816(acc[2*ntp+1],   a0, b[2], b[3]);
                    mma16816(acc[8+2*ntp],   a1, b[0], b[1]);
                    mma16816(acc[8+2*ntp+1], a1, b[2], b[3]);
                }
            }
        }

        // epilogue for this N-half
        #pragma unroll
        for (int f = 0; f < 2; ++f) {
            int r0 = row0 + pm * 32 + f * 16 + g;
            #pragma unroll
            for (int nt = 0; nt < 8; ++nt) {
                int col0 = nh * 256 + pn * 64 + nt * 8 + qd * 2;
                float2 bb = *reinterpret_cast<const float2*>(bu + col0);
                const float* a = acc[f * 8 + nt];
                float2 o0 = make_float2(a[0] + bb.x, a[1] + bb.y);
                float2 o1 = make_float2(a[2] + bb.x, a[3] + bb.y);
                *reinterpret_cast<float2*>(out + (size_t)r0 * E + col0)       = o0;
                *reinterpret_cast<float2*>(out + (size_t)(r0 + 8) * E + col0) = o1;
            }
        }
    }
}

// ============================ launch =======================================
extern "C" void kernel_launch(void* const* d_in, const int* in_sizes, int n_in,
                              void* d_out, int out_size)
{
    const float* x  = (const float*)d_in[0];
    const float* Wq = (const float*)d_in[1];
    const float* bq = (const float*)d_in[2];
    const float* Wk = (const float*)d_in[3];
    const float* bk = (const float*)d_in[4];
    const float* Wv = (const float*)d_in[5];
    const float* bv = (const float*)d_in[6];
    const float* Wu = (const float*)d_in[7];
    const float* bu = (const float*)d_in[8];
    float* out = (float*)d_out;

    const int Nrows = in_sizes[0] / E;
    const int tiles = Nrows / TM;   // 2048

    cudaFuncSetAttribute(fused_sparse_attn,
                         cudaFuncAttributeMaxDynamicSharedMemorySize, SMEM_TOTAL);

    prep_qkv<<<(H * 3 * S * S + 255) / 256, 256>>>(Wq, Wk, Wv);
    prep_wu<<<(E * E + 255) / 256, 256>>>(Wu);
    fused_sparse_attn<<<tiles, 256, SMEM_TOTAL>>>(x, bq, bk, bv, bu, out);
}

// round 8
// speedup vs baseline: 7.0747x; 1.0509x over previous
#include <cuda_runtime.h>
#include <cuda_fp16.h>
#include <cstdint>

// ============================ problem constants ============================
constexpr int E = 512, H = 8, S = 64, TM = 64;

// ============================ device scratch (weights only) ================
// per head: {q_hi, k_hi, v_hi} 64x64 fp16 [s][t] SW128 tiles (8KB each) = 24KB/head
__device__ __align__(1024) unsigned char g_wqkv[H * 3 * 8192];
// Wu_hi chunks: bidx = nh*8 + kc -> [64k x 256n] fp16 swz512, 32KB each (512KB total)
__device__ __align__(1024) unsigned char g_wub[16 * 32768];

// ============================ helpers ======================================
__device__ __forceinline__ uint32_t smem_u32(const void* p) {
    uint32_t a;
    asm("{ .reg .u64 t; cvta.to.shared.u64 t, %1; cvt.u32.u64 %0, t; }" : "=r"(a) : "l"(p));
    return a;
}
__host__ __device__ __forceinline__ uint32_t swz128(uint32_t o) { return o ^ ((o >> 3) & 0x70); }
__host__ __device__ __forceinline__ uint32_t swz512(uint32_t o) { return o ^ ((o >> 5) & 0x70); }

__device__ __forceinline__ void ldsm_x4(uint32_t (&r)[4], uint32_t a) {
    asm volatile("ldmatrix.sync.aligned.m8n8.x4.shared.b16 {%0,%1,%2,%3}, [%4];"
        : "=r"(r[0]), "=r"(r[1]), "=r"(r[2]), "=r"(r[3]) : "r"(a));
}
__device__ __forceinline__ void ldsm_x4t(uint32_t (&r)[4], uint32_t a) {
    asm volatile("ldmatrix.sync.aligned.m8n8.x4.trans.shared.b16 {%0,%1,%2,%3}, [%4];"
        : "=r"(r[0]), "=r"(r[1]), "=r"(r[2]), "=r"(r[3]) : "r"(a));
}
__device__ __forceinline__ void mma16816(float (&d)[4], const uint32_t (&a)[4],
                                         uint32_t b0, uint32_t b1) {
    asm volatile("mma.sync.aligned.m16n8k16.row.col.f32.f16.f16.f32 "
        "{%0,%1,%2,%3}, {%4,%5,%6,%7}, {%8,%9}, {%0,%1,%2,%3};"
        : "+f"(d[0]), "+f"(d[1]), "+f"(d[2]), "+f"(d[3])
        : "r"(a[0]), "r"(a[1]), "r"(a[2]), "r"(a[3]), "r"(b0), "r"(b1));
}
__device__ __forceinline__ void cp16(uint32_t dst, const void* src) {
    asm volatile("cp.async.cg.shared.global [%0], [%1], 16;" :: "r"(dst), "l"(src));
}
#define CP_COMMIT() asm volatile("cp.async.commit_group;" ::: "memory")
#define CP_WAIT(n)  asm volatile("cp.async.wait_group %0;" :: "n"(n) : "memory")

__device__ __forceinline__ uint32_t pack2h(__half a, __half b) {
    __half2 p(a, b);
    return *reinterpret_cast<uint32_t*>(&p);
}

// ============================ prep kernels =================================
// mats: 0=q_hi, 1=k_hi, 2=v_hi ; tile layout [s-rows][t-cols] fp16 SW128
__global__ void prep_qkv(const float* __restrict__ Wq, const float* __restrict__ Wk,
                         const float* __restrict__ Wv) {
    int idx = blockIdx.x * 256 + threadIdx.x;
    if (idx >= H * 3 * S * S) return;
    int h = idx / (3 * S * S);
    int mat = (idx >> 12) % 3;
    int s = (idx >> 6) & 63, t = idx & 63;
    const float* W = (mat == 0) ? Wq : ((mat == 1) ? Wk : Wv);
    float v = W[(h * S + s) * S + t];
    uint32_t off = swz128((uint32_t)(s * 128 + t * 2));
    *reinterpret_cast<__half*>(g_wqkv + (size_t)(h * 3 + mat) * 8192 + off) = __float2half(v);
}
// Wu_hi: chunk bidx = (n>>8)*8 + (k>>6): [64k x 256n] fp16 swz512
__global__ void prep_wu(const float* __restrict__ Wu) {
    int idx = blockIdx.x * 256 + threadIdx.x;
    if (idx >= E * E) return;
    int k = idx >> 9, n = idx & 511;
    int kc = k >> 6, kk = k & 63, nh = n >> 8, nn = n & 255;
    size_t base = (size_t)(nh * 8 + kc) * 32768;
    uint32_t off = swz512((uint32_t)(kk * 512 + nn * 2));
    *reinterpret_cast<__half*>(g_wub + base + off) = __float2half(Wu[idx]);
}

// ============================ fused kernel =================================
// smem map (bytes):
//   sT   @ 0      : 8 tiles [64r x 64k] fp16 SW128, 8KB each (head h = k-chunk h) = 64KB
//   BUF0 @ 65536  : phase2 B buffer 0 (64KB = two 32KB n-halves of a k-chunk)
//                   phase1 overlay: W head-pair (48KB) @65536 + sX (16KB) @114688
//   BUF1 @ 131072 : phase2 B buffer 1 (64KB)
constexpr uint32_t ST = 0, BUF = 65536, SX = 114688;
constexpr uint32_t SMEM_TOTAL = 196608;

__global__ __launch_bounds__(256, 1)
void fused_sparse_attn(const float* __restrict__ x,
                       const float* __restrict__ bq, const float* __restrict__ bk,
                       const float* __restrict__ bv,
                       const float* __restrict__ bu, float* __restrict__ out)
{
    extern __shared__ unsigned char smem[];
    const uint32_t sb = smem_u32(smem);
    const int tid = threadIdx.x, lane = tid & 31, wid = tid >> 5;
    const int row0 = blockIdx.x * TM;
    const float SC = 0.04419417382415922f;   // 1/sqrt(512)

    const int g  = lane >> 2;
    const int qd = lane & 3;
    const uint32_t hiSel = (uint32_t)((lane >> 4) << 4);

    // ===================== Phase 1: QKV + softmax -> sT ====================
    const int lh = wid >> 2;                  // local head in pair
    const int wm = wid & 3;                   // 16-row m position
    const uint32_t aRow = (uint32_t)(wm * 16 + (lane & 15));

    for (int hp = 0; hp < 4; ++hp) {
        // -- stage W head-pair (pre-swizzled, 48KB contiguous) --
        {
            const char* src = (const char*)g_wqkv + (size_t)hp * 49152;
            #pragma unroll
            for (int i = 0; i < 12; ++i) {
                uint32_t o = (uint32_t)(tid + i * 256) * 16;
                cp16(sb + BUF + o, src + o);
            }
            CP_COMMIT();
        }
        // -- stage x slice (hi only): 64 rows x 128 cols fp16 --
        #pragma unroll
        for (int i = 0; i < 8; ++i) {
            int idx = tid + i * 256;
            int r = idx >> 5, c4 = idx & 31;
            float4 xv = *reinterpret_cast<const float4*>(
                x + (size_t)(row0 + r) * E + hp * 128 + c4 * 4);
            uint32_t base = SX + (uint32_t)(c4 >> 4) * 8192;
            uint32_t off = swz128((uint32_t)(r * 128 + (c4 & 15) * 8));
            *reinterpret_cast<uint2*>(smem + base + off) =
                make_uint2(pack2h(__float2half(xv.x), __float2half(xv.y)),
                           pack2h(__float2half(xv.z), __float2half(xv.w)));
        }
        CP_WAIT(0);
        __syncthreads();

        // -- mma: this warp = head hp*2+lh, rows wm*16..+15, all 64 cols --
        const int h = hp * 2 + lh;
        float aq[8][4], ak[8][4], av[8][4];
        #pragma unroll
        for (int nt = 0; nt < 8; ++nt)
            #pragma unroll
            for (int c = 0; c < 4; ++c) { aq[nt][c] = 0.f; ak[nt][c] = 0.f; av[nt][c] = 0.f; }

        const uint32_t xbase = sb + SX + (uint32_t)lh * 8192;
        const uint32_t wbase = sb + BUF + (uint32_t)lh * 24576;

        #pragma unroll
        for (int ks = 0; ks < 4; ++ks) {
            uint32_t aHi[4];
            ldsm_x4(aHi, xbase + swz128(aRow * 128 + (uint32_t)ks * 32 + hiSel));
            #pragma unroll
            for (int ntp = 0; ntp < 4; ++ntp) {
                uint32_t boff = swz128((uint32_t)(ks * 16 + (lane & 15)) * 128
                                       + (uint32_t)ntp * 32 + hiSel);
                uint32_t bQ[4], bK[4], bV[4];
                ldsm_x4t(bQ, wbase + boff);
                ldsm_x4t(bK, wbase + 8192  + boff);
                ldsm_x4t(bV, wbase + 16384 + boff);
                mma16816(aq[2*ntp],   aHi, bQ[0], bQ[1]);
                mma16816(aq[2*ntp+1], aHi, bQ[2], bQ[3]);
                mma16816(ak[2*ntp],   aHi, bK[0], bK[1]);
                mma16816(ak[2*ntp+1], aHi, bK[2], bK[3]);
                mma16816(av[2*ntp],   aHi, bV[0], bV[1]);
                mma16816(av[2*ntp+1], aHi, bV[2], bV[3]);
            }
        }

        // -- softmax (quad-local) + t -> sT tile h --
        const float* bqh = bq + h * S;
        const float* bkh = bk + h * S;
        const float* bvh = bv + h * S;
        #pragma unroll
        for (int rr = 0; rr < 2; ++rr) {
            float ev[16], vv[16];
            float ssum = 0.f;
            #pragma unroll
            for (int nt = 0; nt < 8; ++nt) {
                int col0 = nt * 8 + qd * 2;
                float2 b1 = *reinterpret_cast<const float2*>(bqh + col0);
                float2 b2 = *reinterpret_cast<const float2*>(bkh + col0);
                float2 b3 = *reinterpret_cast<const float2*>(bvh + col0);
                float q0 = aq[nt][rr*2+0] + b1.x, q1 = aq[nt][rr*2+1] + b1.y;
                float k0 = ak[nt][rr*2+0] + b2.x, k1 = ak[nt][rr*2+1] + b2.y;
                float e0 = __expf(q0 * k0 * SC), e1 = __expf(q1 * k1 * SC);
                ev[nt*2] = e0; ev[nt*2+1] = e1; ssum += e0 + e1;
                vv[nt*2]   = av[nt][rr*2+0] + b3.x;
                vv[nt*2+1] = av[nt][rr*2+1] + b3.y;
            }
            ssum += __shfl_xor_sync(0xffffffffu, ssum, 1);
            ssum += __shfl_xor_sync(0xffffffffu, ssum, 2);
            float inv = 1.0f / ssum;
            int rt = wm * 16 + g + rr * 8;
            #pragma unroll
            for (int nt = 0; nt < 8; ++nt) {
                float t0 = ev[nt*2]   * inv * vv[nt*2];
                float t1 = ev[nt*2+1] * inv * vv[nt*2+1];
                uint32_t off = (uint32_t)h * 8192
                             + swz128((uint32_t)(rt * 128 + (nt * 8 + qd * 2) * 2));
                *reinterpret_cast<uint32_t*>(smem + ST + off) =
                    pack2h(__float2half(t0), __float2half(t1));
            }
        }
        __syncthreads();   // W/sX region reuse next round; sT coherent after last
    }

    // ===================== Phase 2: out = t @ Wu_hi + bu ===================
    // warp = 32 rows x 128 cols: pm in {0,1}, pn in {0..3}; 8 k-chunk steps
    const int pm = wid & 1;
    const int pn = wid >> 1;

    auto load_chunk = [&](int kc, int buf) {
        uint32_t d = sb + BUF + (uint32_t)buf * 65536;
        const char* s0 = (const char*)g_wub + (size_t)kc * 32768;        // n-half 0
        const char* s1 = (const char*)g_wub + (size_t)(8 + kc) * 32768;  // n-half 1
        #pragma unroll
        for (int i = 0; i < 8; ++i) {
            uint32_t o = (uint32_t)(tid + i * 256) * 16;
            cp16(d + o,         s0 + o);
            cp16(d + 32768 + o, s1 + o);
        }
    };

    load_chunk(0, 0);
    CP_COMMIT();

    float acc[2][16][4];
    #pragma unroll
    for (int m = 0; m < 2; ++m)
        #pragma unroll
        for (int nf = 0; nf < 16; ++nf)
            #pragma unroll
            for (int c = 0; c < 4; ++c) acc[m][nf][c] = 0.f;

    for (int kc = 0; kc < 8; ++kc) {
        CP_WAIT(0);
        __syncthreads();
        if (kc + 1 < 8) { load_chunk(kc + 1, (kc + 1) & 1); CP_COMMIT(); }

        uint32_t bb = sb + BUF + (uint32_t)(kc & 1) * 65536;
        uint32_t tA = sb + ST + (uint32_t)kc * 8192;
        #pragma unroll
        for (int ksg = 0; ksg < 4; ++ksg) {
            uint32_t a0[4], a1[4];
            uint32_t kOff = (uint32_t)ksg * 32 + hiSel;
            ldsm_x4(a0, tA + swz128((uint32_t)(pm * 32 + (lane & 15)) * 128 + kOff));
            ldsm_x4(a1, tA + swz128((uint32_t)(pm * 32 + 16 + (lane & 15)) * 128 + kOff));
            #pragma unroll
            for (int ntp = 0; ntp < 8; ++ntp) {
                uint32_t colB = (uint32_t)(pn * 256 + ntp * 32);   // byte col offset
                uint32_t addr = bb + ((colB >> 9) << 15)
                              + swz512((uint32_t)(ksg * 16 + (lane & 15)) * 512
                                       + (colB & 511) + hiSel);
                uint32_t b[4];
                ldsm_x4t(b, addr);
                mma16816(acc[0][2*ntp],   a0, b[0], b[1]);
                mma16816(acc[0][2*ntp+1], a0, b[2], b[3]);
                mma16816(acc[1][2*ntp],   a1, b[0], b[1]);
                mma16816(acc[1][2*ntp+1], a1, b[2], b[3]);
            }
        }
    }

    // -- epilogue: + bu, store --
    #pragma unroll
    for (int m = 0; m < 2; ++m) {
        int r0 = row0 + pm * 32 + m * 16 + g;
        #pragma unroll
        for (int nf = 0; nf < 16; ++nf) {
            int col0 = pn * 128 + nf * 8 + qd * 2;
            float2 bb = *reinterpret_cast<const float2*>(bu + col0);
            const float* a = acc[m][nf];
            float2 o0 = make_float2(a[0] + bb.x, a[1] + bb.y);
            float2 o1 = make_float2(a[2] + bb.x, a[3] + bb.y);
            *reinterpret_cast<float2*>(out + (size_t)r0 * E + col0)       = o0;
            *reinterpret_cast<float2*>(out + (size_t)(r0 + 8) * E + col0) = o1;
        }
    }
}

// ============================ launch =======================================
extern "C" void kernel_launch(void* const* d_in, const int* in_sizes, int n_in,
                              void* d_out, int out_size)
{
    const float* x  = (const float*)d_in[0];
    const float* Wq = (const float*)d_in[1];
    const float* bq = (const float*)d_in[2];
    const float* Wk = (const float*)d_in[3];
    const float* bk = (const float*)d_in[4];
    const float* Wv = (const float*)d_in[5];
    const float* bv = (const float*)d_in[6];
    const float* Wu = (const float*)d_in[7];
    const float* bu = (const float*)d_in[8];
    float* out = (float*)d_out;

    const int Nrows = in_sizes[0] / E;
    const int tiles = Nrows / TM;   // 2048

    cudaFuncSetAttribute(fused_sparse_attn,
                         cudaFuncAttributeMaxDynamicSharedMemorySize, SMEM_TOTAL);

    prep_qkv<<<(H * 3 * S * S + 255) / 256, 256>>>(Wq, Wk, Wv);
    prep_wu<<<(E * E + 255) / 256, 256>>>(Wu);
    fused_sparse_attn<<<tiles, 256, SMEM_TOTAL>>>(x, bq, bk, bv, bu, out);
}

// round 9
// speedup vs baseline: 7.9435x; 1.1228x over previous
#include <cuda_runtime.h>
#include <cuda_fp16.h>
#include <cstdint>

// ============================ problem constants ============================
constexpr int E = 512, H = 8, S = 64, TM = 64;

// ============================ device scratch (weights only) ================
// per head: {q_hi, k_hi, v_hi} 64x64 fp16 [s][t] SW128 tiles (8KB each) = 24KB/head
__device__ __align__(1024) unsigned char g_wqkv[H * 3 * 8192];
// Wu_hi chunks: bidx = nh*8 + kc -> [64k x 256n] fp16 swz512, 32KB each (512KB total)
__device__ __align__(1024) unsigned char g_wub[16 * 32768];

// ============================ helpers ======================================
__device__ __forceinline__ uint32_t smem_u32(const void* p) {
    uint32_t a;
    asm("{ .reg .u64 t; cvta.to.shared.u64 t, %1; cvt.u32.u64 %0, t; }" : "=r"(a) : "l"(p));
    return a;
}
__host__ __device__ __forceinline__ uint32_t swz128(uint32_t o) { return o ^ ((o >> 3) & 0x70); }
__host__ __device__ __forceinline__ uint32_t swz512(uint32_t o) { return o ^ ((o >> 5) & 0x70); }

__device__ __forceinline__ void ldsm_x4(uint32_t (&r)[4], uint32_t a) {
    asm volatile("ldmatrix.sync.aligned.m8n8.x4.shared.b16 {%0,%1,%2,%3}, [%4];"
        : "=r"(r[0]), "=r"(r[1]), "=r"(r[2]), "=r"(r[3]) : "r"(a));
}
__device__ __forceinline__ void ldsm_x4t(uint32_t (&r)[4], uint32_t a) {
    asm volatile("ldmatrix.sync.aligned.m8n8.x4.trans.shared.b16 {%0,%1,%2,%3}, [%4];"
        : "=r"(r[0]), "=r"(r[1]), "=r"(r[2]), "=r"(r[3]) : "r"(a));
}
__device__ __forceinline__ void mma16816(float (&d)[4], const uint32_t (&a)[4],
                                         uint32_t b0, uint32_t b1) {
    asm volatile("mma.sync.aligned.m16n8k16.row.col.f32.f16.f16.f32 "
        "{%0,%1,%2,%3}, {%4,%5,%6,%7}, {%8,%9}, {%0,%1,%2,%3};"
        : "+f"(d[0]), "+f"(d[1]), "+f"(d[2]), "+f"(d[3])
        : "r"(a[0]), "r"(a[1]), "r"(a[2]), "r"(a[3]), "r"(b0), "r"(b1));
}
__device__ __forceinline__ void cp16(uint32_t dst, const void* src) {
    asm volatile("cp.async.cg.shared.global [%0], [%1], 16;" :: "r"(dst), "l"(src));
}
#define CP_COMMIT() asm volatile("cp.async.commit_group;" ::: "memory")
#define CP_WAIT(n)  asm volatile("cp.async.wait_group %0;" :: "n"(n) : "memory")

__device__ __forceinline__ uint32_t pack2h(__half a, __half b) {
    __half2 p(a, b);
    return *reinterpret_cast<uint32_t*>(&p);
}
__device__ __forceinline__ uint32_t packf2(float2 v) {
    return pack2h(__float2half(v.x), __float2half(v.y));
}

// ============================ prep kernels =================================
// mats: 0=q_hi, 1=k_hi, 2=v_hi ; tile layout [s-rows][t-cols] fp16 SW128
__global__ void prep_qkv(const float* __restrict__ Wq, const float* __restrict__ Wk,
                         const float* __restrict__ Wv) {
    int idx = blockIdx.x * 256 + threadIdx.x;
    if (idx >= H * 3 * S * S) return;
    int h = idx / (3 * S * S);
    int mat = (idx >> 12) % 3;
    int s = (idx >> 6) & 63, t = idx & 63;
    const float* W = (mat == 0) ? Wq : ((mat == 1) ? Wk : Wv);
    float v = W[(h * S + s) * S + t];
    uint32_t off = swz128((uint32_t)(s * 128 + t * 2));
    *reinterpret_cast<__half*>(g_wqkv + (size_t)(h * 3 + mat) * 8192 + off) = __float2half(v);
}
// Wu_hi: chunk bidx = (n>>8)*8 + (k>>6): [64k x 256n] fp16 swz512
__global__ void prep_wu(const float* __restrict__ Wu) {
    int idx = blockIdx.x * 256 + threadIdx.x;
    if (idx >= E * E) return;
    int k = idx >> 9, n = idx & 511;
    int kc = k >> 6, kk = k & 63, nh = n >> 8, nn = n & 255;
    size_t base = (size_t)(nh * 8 + kc) * 32768;
    uint32_t off = swz512((uint32_t)(kk * 512 + nn * 2));
    *reinterpret_cast<__half*>(g_wub + base + off) = __float2half(Wu[idx]);
}

// ============================ fused kernel =================================
// smem map (bytes), 112KB total -> 2 CTAs/SM:
//   sT  @ 0     : 8 tiles [64r x 64k] fp16 SW128 (head h = k-chunk h) = 64KB
//   BUF @ 65536 : phase1 = W head-pair (48KB); phase2 = B 2 x 16KB sub-chunks
constexpr uint32_t ST = 0, BUF = 65536;
constexpr uint32_t SMEM_TOTAL = 114688;

__global__ __launch_bounds__(256, 2)
void fused_sparse_attn(const float* __restrict__ x,
                       const float* __restrict__ bq, const float* __restrict__ bk,
                       const float* __restrict__ bv,
                       const float* __restrict__ bu, float* __restrict__ out)
{
    extern __shared__ unsigned char smem[];
    const uint32_t sb = smem_u32(smem);
    const int tid = threadIdx.x, lane = tid & 31, wid = tid >> 5;
    const int row0 = blockIdx.x * TM;
    const float SC = 0.04419417382415922f;   // 1/sqrt(512)

    const int g  = lane >> 2;
    const int qd = lane & 3;
    const uint32_t hiSel = (uint32_t)((lane >> 4) << 4);

    // ===================== Phase 1: QKV + softmax -> sT ====================
    const int lh = wid >> 2;                  // local head in pair
    const int wm = wid & 3;                   // 16-row m position

    for (int hp = 0; hp < 4; ++hp) {
        // -- stage W head-pair (pre-swizzled, 48KB contiguous) --
        {
            const char* src = (const char*)g_wqkv + (size_t)hp * 49152;
            #pragma unroll
            for (int i = 0; i < 12; ++i) {
                uint32_t o = (uint32_t)(tid + i * 256) * 16;
                cp16(sb + BUF + o, src + o);
            }
            CP_COMMIT();
        }
        // -- A fragments straight from gmem (overlaps the cp.async wait) --
        uint32_t aF[4][4];
        {
            const float* xr0 = x + (size_t)(row0 + wm * 16 + g) * E + hp * 128 + lh * 64;
            const float* xr1 = xr0 + 8 * (size_t)E;
            #pragma unroll
            for (int ks = 0; ks < 4; ++ks) {
                int c = ks * 16 + qd * 2;
                aF[ks][0] = packf2(*reinterpret_cast<const float2*>(xr0 + c));
                aF[ks][1] = packf2(*reinterpret_cast<const float2*>(xr1 + c));
                aF[ks][2] = packf2(*reinterpret_cast<const float2*>(xr0 + c + 8));
                aF[ks][3] = packf2(*reinterpret_cast<const float2*>(xr1 + c + 8));
            }
        }
        CP_WAIT(0);
        __syncthreads();

        const int h = hp * 2 + lh;
        const uint32_t wbase = sb + BUF + (uint32_t)lh * 24576;

        float aq[8][4], ak[8][4];
        #pragma unroll
        for (int nt = 0; nt < 8; ++nt)
            #pragma unroll
            for (int c = 0; c < 4; ++c) { aq[nt][c] = 0.f; ak[nt][c] = 0.f; }

        // pass A: q and k
        #pragma unroll
        for (int ks = 0; ks < 4; ++ks) {
            #pragma unroll
            for (int ntp = 0; ntp < 4; ++ntp) {
                uint32_t boff = swz128((uint32_t)(ks * 16 + (lane & 15)) * 128
                                       + (uint32_t)ntp * 32 + hiSel);
                uint32_t bQ[4], bK[4];
                ldsm_x4t(bQ, wbase + boff);
                ldsm_x4t(bK, wbase + 8192 + boff);
                mma16816(aq[2*ntp],   aF[ks], bQ[0], bQ[1]);
                mma16816(aq[2*ntp+1], aF[ks], bQ[2], bQ[3]);
                mma16816(ak[2*ntp],   aF[ks], bK[0], bK[1]);
                mma16816(ak[2*ntp+1], aF[ks], bK[2], bK[3]);
            }
        }
        // pass B: v
        float av[8][4];
        #pragma unroll
        for (int nt = 0; nt < 8; ++nt)
            #pragma unroll
            for (int c = 0; c < 4; ++c) av[nt][c] = 0.f;
        #pragma unroll
        for (int ks = 0; ks < 4; ++ks) {
            #pragma unroll
            for (int ntp = 0; ntp < 4; ++ntp) {
                uint32_t boff = swz128((uint32_t)(ks * 16 + (lane & 15)) * 128
                                       + (uint32_t)ntp * 32 + hiSel);
                uint32_t bV[4];
                ldsm_x4t(bV, wbase + 16384 + boff);
                mma16816(av[2*ntp],   aF[ks], bV[0], bV[1]);
                mma16816(av[2*ntp+1], aF[ks], bV[2], bV[3]);
            }
        }

        // -- softmax (quad-local), reuse aq<-e, av<-v+bias --
        const float* bqh = bq + h * S;
        const float* bkh = bk + h * S;
        const float* bvh = bv + h * S;
        float ssum0 = 0.f, ssum1 = 0.f;
        #pragma unroll
        for (int nt = 0; nt < 8; ++nt) {
            int col0 = nt * 8 + qd * 2;
            float2 b1 = *reinterpret_cast<const float2*>(bqh + col0);
            float2 b2 = *reinterpret_cast<const float2*>(bkh + col0);
            float2 b3 = *reinterpret_cast<const float2*>(bvh + col0);
            float e;
            e = __expf((aq[nt][0] + b1.x) * (ak[nt][0] + b2.x) * SC); aq[nt][0] = e; ssum0 += e;
            e = __expf((aq[nt][1] + b1.y) * (ak[nt][1] + b2.y) * SC); aq[nt][1] = e; ssum0 += e;
            e = __expf((aq[nt][2] + b1.x) * (ak[nt][2] + b2.x) * SC); aq[nt][2] = e; ssum1 += e;
            e = __expf((aq[nt][3] + b1.y) * (ak[nt][3] + b2.y) * SC); aq[nt][3] = e; ssum1 += e;
            av[nt][0] += b3.x; av[nt][1] += b3.y;
            av[nt][2] += b3.x; av[nt][3] += b3.y;
        }
        ssum0 += __shfl_xor_sync(0xffffffffu, ssum0, 1);
        ssum0 += __shfl_xor_sync(0xffffffffu, ssum0, 2);
        ssum1 += __shfl_xor_sync(0xffffffffu, ssum1, 1);
        ssum1 += __shfl_xor_sync(0xffffffffu, ssum1, 2);
        const float inv0 = 1.0f / ssum0, inv1 = 1.0f / ssum1;

        {
            int rt0 = wm * 16 + g;
            #pragma unroll
            for (int nt = 0; nt < 8; ++nt) {
                uint32_t cb = (uint32_t)((nt * 8 + qd * 2) * 2);
                uint32_t offBase = (uint32_t)h * 8192;
                float t0 = aq[nt][0] * inv0 * av[nt][0];
                float t1 = aq[nt][1] * inv0 * av[nt][1];
                float t2 = aq[nt][2] * inv1 * av[nt][2];
                float t3 = aq[nt][3] * inv1 * av[nt][3];
                *reinterpret_cast<uint32_t*>(smem + ST + offBase
                    + swz128((uint32_t)rt0 * 128 + cb)) =
                    pack2h(__float2half(t0), __float2half(t1));
                *reinterpret_cast<uint32_t*>(smem + ST + offBase
                    + swz128((uint32_t)(rt0 + 8) * 128 + cb)) =
                    pack2h(__float2half(t2), __float2half(t3));
            }
        }
        __syncthreads();   // BUF (W) safe to overwrite; sT coherent after last hp
    }

    // ===================== Phase 2: out = t @ Wu_hi + bu ===================
    // warp = 32 rows x 64 cols: pm in {0,1}, pn in {0..3}; nh sweep over 2 halves
    const int pm = wid & 1;
    const int pn = wid >> 1;

    // B sub-chunk: step s (0..31): nh=s>>4, kc=(s>>1)&7, half=s&1 -> 16KB contiguous
    auto load_sub = [&](int s, int buf) {
        int nh = s >> 4, kc = (s >> 1) & 7, half = s & 1;
        const char* src = (const char*)g_wub + (size_t)(nh * 8 + kc) * 32768
                        + (size_t)half * 16384;
        uint32_t d = sb + BUF + (uint32_t)buf * 16384;
        #pragma unroll
        for (int i = 0; i < 4; ++i) {
            uint32_t o = (uint32_t)(tid + i * 256) * 16;
            cp16(d + o, src + o);
        }
    };

    load_sub(0, 0);
    CP_COMMIT();

    for (int nh = 0; nh < 2; ++nh) {
        float acc[16][4];
        #pragma unroll
        for (int nf = 0; nf < 16; ++nf)
            #pragma unroll
            for (int c = 0; c < 4; ++c) acc[nf][c] = 0.f;

        for (int s16 = 0; s16 < 16; ++s16) {
            int s = nh * 16 + s16;
            CP_WAIT(0);
            __syncthreads();
            if (s + 1 < 32) { load_sub(s + 1, (s + 1) & 1); CP_COMMIT(); }

            int kc = s16 >> 1, half = s16 & 1;
            uint32_t bb = sb + BUF + (uint32_t)(s & 1) * 16384;
            uint32_t tA = sb + ST + (uint32_t)kc * 8192;
            #pragma unroll
            for (int ksg = 0; ksg < 2; ++ksg) {
                uint32_t kOff = (uint32_t)(half * 64 + ksg * 32) + hiSel;
                uint32_t a0[4], a1[4];
                ldsm_x4(a0, tA + swz128((uint32_t)(pm * 32 + (lane & 15)) * 128 + kOff));
                ldsm_x4(a1, tA + swz128((uint32_t)(pm * 32 + 16 + (lane & 15)) * 128 + kOff));
                #pragma unroll
                for (int ntp = 0; ntp < 4; ++ntp) {
                    uint32_t boff = swz512((uint32_t)(ksg * 16 + (lane & 15)) * 512
                                           + (uint32_t)(pn * 128 + ntp * 32) + hiSel);
                    uint32_t b[4];
                    ldsm_x4t(b, bb + boff);
                    mma16816(acc[2*ntp],     a0, b[0], b[1]);
                    mma16816(acc[2*ntp+1],   a0, b[2], b[3]);
                    mma16816(acc[8+2*ntp],   a1, b[0], b[1]);
                    mma16816(acc[8+2*ntp+1], a1, b[2], b[3]);
                }
            }
        }

        // epilogue for this N-half
        #pragma unroll
        for (int m = 0; m < 2; ++m) {
            int r0 = row0 + pm * 32 + m * 16 + g;
            #pragma unroll
            for (int nf = 0; nf < 8; ++nf) {
                int col0 = nh * 256 + pn * 64 + nf * 8 + qd * 2;
                float2 bb2 = *reinterpret_cast<const float2*>(bu + col0);
                const float* a = acc[m * 8 + nf];
                float2 o0 = make_float2(a[0] + bb2.x, a[1] + bb2.y);
                float2 o1 = make_float2(a[2] + bb2.x, a[3] + bb2.y);
                *reinterpret_cast<float2*>(out + (size_t)r0 * E + col0)       = o0;
                *reinterpret_cast<float2*>(out + (size_t)(r0 + 8) * E + col0) = o1;
            }
        }
    }
}

// ============================ launch =======================================
extern "C" void kernel_launch(void* const* d_in, const int* in_sizes, int n_in,
                              void* d_out, int out_size)
{
    const float* x  = (const float*)d_in[0];
    const float* Wq = (const float*)d_in[1];
    const float* bq = (const float*)d_in[2];
    const float* Wk = (const float*)d_in[3];
    const float* bk = (const float*)d_in[4];
    const float* Wv = (const float*)d_in[5];
    const float* bv = (const float*)d_in[6];
    const float* Wu = (const float*)d_in[7];
    const float* bu = (const float*)d_in[8];
    float* out = (float*)d_out;

    const int Nrows = in_sizes[0] / E;
    const int tiles = Nrows / TM;   // 2048

    cudaFuncSetAttribute(fused_sparse_attn,
                         cudaFuncAttributeMaxDynamicSharedMemorySize, SMEM_TOTAL);

    prep_qkv<<<(H * 3 * S * S + 255) / 256, 256>>>(Wq, Wk, Wv);
    prep_wu<<<(E * E + 255) / 256, 256>>>(Wu);
    fused_sparse_attn<<<tiles, 256, SMEM_TOTAL>>>(x, bq, bk, bv, bu, out);
}